// round 7
// baseline (speedup 1.0000x reference)
#include <cuda_runtime.h>
#include <cuda_bf16.h>
#include <cstdint>
#include <math.h>

#define MATN 4096
#define NSQL ((size_t)MATN * (size_t)MATN)

// ---------------- static device scratch ----------------
__device__ float g_X0[MATN * MATN];
__device__ float g_X1[MATN * MATN];
__device__ float g_S [MATN * MATN];
__device__ float g_P [MATN * MATN];
__device__ __nv_bfloat16 g_hA [MATN * MATN];
__device__ __nv_bfloat16 g_lA [MATN * MATN];
__device__ __nv_bfloat16 g_hAT[MATN * MATN];
__device__ __nv_bfloat16 g_lAT[MATN * MATN];
__device__ __nv_bfloat16 g_hS [MATN * MATN];
__device__ __nv_bfloat16 g_lS [MATN * MATN];
__device__ __nv_bfloat16 g_hP [MATN * MATN];
__device__ __nv_bfloat16 g_lP [MATN * MATN];
__device__ float g_v[MATN];
__device__ float g_y[MATN];
__device__ float g_part[256];
__device__ float g_scal[4];    // [1]=sigma_ray^2  [2]=tmp norm
__device__ int   g_flag;
__device__ int   g_flagL;

// ---------------- helpers ----------------
__device__ __forceinline__ uint32_t smem_u32(const void* p) {
    uint32_t a;
    asm("{ .reg .u64 t; cvta.to.shared.u64 t, %1; cvt.u32.u64 %0, t; }" : "=r"(a) : "l"(p));
    return a;
}
__device__ __forceinline__ void cp16(uint32_t dst, const void* src) {
    asm volatile("cp.async.cg.shared.global [%0], [%1], 16;" :: "r"(dst), "l"(src));
}
#define CP_COMMIT() asm volatile("cp.async.commit_group;" ::: "memory")
#define CP_WAIT(N)  asm volatile("cp.async.wait_group %0;" :: "n"(N) : "memory")

#define LDSM_X4(r, a)                                                           \
    asm volatile("ldmatrix.sync.aligned.m8n8.x4.shared.b16 {%0,%1,%2,%3}, [%4];" \
        : "=r"((r)[0]), "=r"((r)[1]), "=r"((r)[2]), "=r"((r)[3]) : "r"(a))

__device__ __forceinline__ void mma_bf16(float* d, const uint32_t* a,
                                         uint32_t b0, uint32_t b1) {
    asm volatile(
        "mma.sync.aligned.m16n8k16.row.col.f32.bf16.bf16.f32 "
        "{%0,%1,%2,%3}, {%4,%5,%6,%7}, {%8,%9}, {%0,%1,%2,%3};"
        : "+f"(d[0]), "+f"(d[1]), "+f"(d[2]), "+f"(d[3])
        : "r"(a[0]), "r"(a[1]), "r"(a[2]), "r"(a[3]), "r"(b0), "r"(b1));
}

// ---------------- bf16 tensor-core GEMM (mma.sync) ----------------
// C = sum_s A_s * B_s^T ; POLY=1: C = c2*D + c1*E + c0*I.  Guarded by g_flagL.
// CTA tile 256x128, BK=32, 256 thr (8 warps: 4 row x 2 col, 64x64 each).
// 3-stage cp.async pipeline, dynamic smem.
#define BROW 80
#define A_BYTES (256 * BROW)           // 20480
#define B_BYTES (128 * BROW)           // 10240
#define BUFBYTES (A_BYTES + B_BYTES)   // 30720
#define SMEM_SZ (3 * BUFBYTES)         // 92160

template<int POLY>
__global__ void __launch_bounds__(256, 1)
mma_gemm(const __nv_bfloat16* __restrict__ A0, const __nv_bfloat16* __restrict__ B0,
         const __nv_bfloat16* __restrict__ A1, const __nv_bfloat16* __restrict__ B1,
         const __nv_bfloat16* __restrict__ A2, const __nv_bfloat16* __restrict__ B2,
         int nseg, float* __restrict__ C, const float* __restrict__ E,
         float c0, float c1, float c2)
{
    if (g_flagL) return;
    extern __shared__ __align__(16) char smem[];
    const uint32_t sbase = smem_u32(smem);

    const int tid  = threadIdx.x;
    const int wid  = tid >> 5, lane = tid & 31;
    const int wr   = wid & 3;          // 4 row-warps, 64 rows each
    const int wc   = wid >> 2;         // 2 col-warps, 64 cols each
    const int row0 = blockIdx.y * 256;
    const int col0 = blockIdx.x * 128;

    const __nv_bfloat16* Aseg[3] = {A0, A1, A2};
    const __nv_bfloat16* Bseg[3] = {B0, B1, B2};

    float acc[4][8][4];
    #pragma unroll
    for (int i = 0; i < 4; ++i)
        #pragma unroll
        for (int j = 0; j < 8; ++j)
            #pragma unroll
            for (int k = 0; k < 4; ++k) acc[i][j][k] = 0.f;

    auto load_chunk = [&](int ch, int buf) {
        const int seg = ch >> 7, kc = ch & 127;
        const __nv_bfloat16* Ap = Aseg[seg] + (size_t)row0 * MATN + kc * 32;
        const __nv_bfloat16* Bp = Bseg[seg] + (size_t)col0 * MATN + kc * 32;
        const uint32_t sa = sbase + buf * BUFBYTES;
        const uint32_t sb = sa + A_BYTES;
        #pragma unroll
        for (int p = 0; p < 4; ++p) {         // A: 256 rows x 32 cols
            int q = tid + p * 256;
            int r = q >> 2, s = q & 3;
            cp16(sa + r * BROW + s * 16, Ap + (size_t)r * MATN + s * 8);
        }
        #pragma unroll
        for (int p = 0; p < 2; ++p) {         // B: 128 rows x 32 cols
            int q = tid + p * 256;
            int r = q >> 2, s = q & 3;
            cp16(sb + r * BROW + s * 16, Bp + (size_t)r * MATN + s * 8);
        }
    };

    auto compute_chunk = [&](int buf) {
        const uint32_t sa = sbase + buf * BUFBYTES;
        const uint32_t sb = sa + A_BYTES;
        #pragma unroll
        for (int kk = 0; kk < 2; ++kk) {
            uint32_t af[4][4], bf[4][4];
            #pragma unroll
            for (int mt = 0; mt < 4; ++mt) {
                uint32_t addr = sa + (uint32_t)(wr * 64 + mt * 16 + (lane & 15)) * BROW
                              + kk * 32 + (lane >> 4) * 16;
                LDSM_X4(af[mt], addr);
            }
            #pragma unroll
            for (int bp = 0; bp < 4; ++bp) {
                int grp = lane >> 3, wi = lane & 7;
                uint32_t addr = sb + (uint32_t)(wc * 64 + bp * 16 + wi + (grp >> 1) * 8) * BROW
                              + kk * 32 + (grp & 1) * 16;
                LDSM_X4(bf[bp], addr);
            }
            #pragma unroll
            for (int mt = 0; mt < 4; ++mt)
                #pragma unroll
                for (int nt = 0; nt < 8; ++nt)
                    mma_bf16(acc[mt][nt], af[mt], bf[nt >> 1][(nt & 1) * 2],
                             bf[nt >> 1][(nt & 1) * 2 + 1]);
        }
    };

    const int total = nseg * 128;
    load_chunk(0, 0); CP_COMMIT();
    load_chunk(1, 1); CP_COMMIT();

    for (int ch = 0; ch < total; ++ch) {
        if (ch + 2 < total) load_chunk(ch + 2, (ch + 2) % 3);
        CP_COMMIT();                       // (possibly empty) group each iter
        CP_WAIT(2);
        __syncthreads();
        compute_chunk(ch % 3);
        __syncthreads();
    }

    #pragma unroll
    for (int mt = 0; mt < 4; ++mt) {
        #pragma unroll
        for (int half = 0; half < 2; ++half) {
            const int rg = row0 + wr * 64 + mt * 16 + (lane >> 2) + half * 8;
            const size_t rowbase = (size_t)rg * MATN;
            #pragma unroll
            for (int nt = 0; nt < 8; ++nt) {
                const int cc = col0 + wc * 64 + nt * 8 + (lane & 3) * 2;
                float v0 = acc[mt][nt][half * 2 + 0];
                float v1 = acc[mt][nt][half * 2 + 1];
                if (POLY) {
                    float2 e = *reinterpret_cast<const float2*>(E + rowbase + cc);
                    v0 = c2 * v0 + c1 * e.x + ((rg == cc)     ? c0 : 0.f);
                    v1 = c2 * v1 + c1 * e.y + ((rg == cc + 1) ? c0 : 0.f);
                }
                float2 o = make_float2(v0, v1);
                *reinterpret_cast<float2*>(C + rowbase + cc) = o;
            }
        }
    }
}

// ---------------- small kernels ----------------
__global__ void k_reset() { g_flag = 0; g_flagL = 0; }
__global__ void k_latch() { g_flagL = g_flag; }

__global__ void k_copy_if(const float* __restrict__ src, float* __restrict__ dst) {
    if (!g_flagL) return;
    for (size_t i = (size_t)blockIdx.x * blockDim.x + threadIdx.x; i < NSQL / 4;
         i += (size_t)gridDim.x * blockDim.x)
        reinterpret_cast<float4*>(dst)[i] = reinterpret_cast<const float4*>(src)[i];
}

__global__ void k_sumsq(const float* __restrict__ x, int n, float* __restrict__ part) {
    __shared__ float sm[256];
    float acc = 0.f;
    for (int i = blockIdx.x * blockDim.x + threadIdx.x; i < n; i += gridDim.x * blockDim.x) {
        float v = x[i]; acc = fmaf(v, v, acc);
    }
    sm[threadIdx.x] = acc; __syncthreads();
    for (int s = 128; s > 0; s >>= 1) {
        if (threadIdx.x < s) sm[threadIdx.x] += sm[threadIdx.x + s];
        __syncthreads();
    }
    if (threadIdx.x == 0) part[blockIdx.x] = sm[0];
}
__global__ void k_finish(const float* __restrict__ part, float* __restrict__ dst) {
    __shared__ float sm[256];
    sm[threadIdx.x] = part[threadIdx.x]; __syncthreads();
    for (int s = 128; s > 0; s >>= 1) {
        if (threadIdx.x < s) sm[threadIdx.x] += sm[threadIdx.x + s];
        __syncthreads();
    }
    if (threadIdx.x == 0) *dst = sm[0];
}

__global__ void k_initv(float* v) {
    int j = blockIdx.x * blockDim.x + threadIdx.x;
    if (j < MATN) {
        unsigned h = (unsigned)j * 2654435761u;
        h ^= h >> 13; h *= 0x5bd1e995u; h ^= h >> 15;
        v[j] = ((float)(h & 0xFFFFu) / 65536.0f) - 0.5f + 0.001f;
    }
}
__global__ void k_normalize(float* v, const float* n2) {
    int j = blockIdx.x * blockDim.x + threadIdx.x;
    float s = rsqrtf(*n2 + 1e-30f);
    if (j < MATN) v[j] *= s;
}
__global__ void k_mvn(const float* __restrict__ H, const float* __restrict__ v,
                      float* __restrict__ y) {
    __shared__ float sm[128];
    int r = blockIdx.x;
    const float* row = H + (size_t)r * MATN;
    float acc = 0.f;
    for (int j = threadIdx.x; j < MATN; j += 128) acc = fmaf(row[j], v[j], acc);
    sm[threadIdx.x] = acc; __syncthreads();
    for (int s = 64; s > 0; s >>= 1) {
        if (threadIdx.x < s) sm[threadIdx.x] += sm[threadIdx.x + s];
        __syncthreads();
    }
    if (threadIdx.x == 0) y[r] = sm[0];
}
__global__ void k_mvt(const float* __restrict__ H, const float* __restrict__ y,
                      float* __restrict__ z) {
    __shared__ float sm[256];
    int tj = threadIdx.x & 31, gi = threadIdx.x >> 5;
    int j = blockIdx.x * 32 + tj;
    float acc = 0.f;
    for (int i = gi * 512; i < gi * 512 + 512; ++i)
        acc = fmaf(H[(size_t)i * MATN + j], y[i], acc);
    sm[threadIdx.x] = acc; __syncthreads();
    if (threadIdx.x < 32) {
        float t = 0.f;
        #pragma unroll
        for (int g = 0; g < 8; ++g) t += sm[threadIdx.x + 32 * g];
        z[j] = t;
    }
}

__global__ void k_splitT(const float* __restrict__ X,
                         __nv_bfloat16* __restrict__ hi, __nv_bfloat16* __restrict__ lo,
                         __nv_bfloat16* __restrict__ hiT, __nv_bfloat16* __restrict__ loT,
                         float scT, int prescale) {
    if (g_flagL) return;
    __shared__ float t[32][33];
    float s = prescale ? (rsqrtf(g_scal[1] + 1e-30f) / 1.10f) : 1.0f;
    int x0 = blockIdx.x * 32, y0 = blockIdx.y * 32;
    #pragma unroll
    for (int j = 0; j < 32; j += 8) {
        int r = y0 + threadIdx.y + j, c = x0 + threadIdx.x;
        float v = X[(size_t)r * MATN + c] * s;
        t[threadIdx.y + j][threadIdx.x] = v;
        __nv_bfloat16 h = __float2bfloat16(v);
        hi[(size_t)r * MATN + c] = h;
        lo[(size_t)r * MATN + c] = __float2bfloat16(v - __bfloat162float(h));
    }
    __syncthreads();
    #pragma unroll
    for (int j = 0; j < 32; j += 8) {
        int r = x0 + threadIdx.y + j, c = y0 + threadIdx.x;
        float v = t[threadIdx.x][threadIdx.y + j];
        __nv_bfloat16 h = __float2bfloat16(v);
        hiT[(size_t)r * MATN + c] = h;
        loT[(size_t)r * MATN + c] = __float2bfloat16((v - __bfloat162float(h)) * scT);
    }
}

__global__ void k_symsplit(float* __restrict__ S,
                           __nv_bfloat16* __restrict__ hi, __nv_bfloat16* __restrict__ lo,
                           float sc) {
    if (g_flagL) return;
    __shared__ float ta[32][33], tb[32][33];
    int bi = blockIdx.y, bj = blockIdx.x;
    if (bj < bi) return;
    int i0 = bi * 32, j0 = bj * 32;
    #pragma unroll
    for (int j = 0; j < 32; j += 8) {
        ta[threadIdx.y + j][threadIdx.x] = S[(size_t)(i0 + threadIdx.y + j) * MATN + j0 + threadIdx.x];
        tb[threadIdx.y + j][threadIdx.x] = S[(size_t)(j0 + threadIdx.y + j) * MATN + i0 + threadIdx.x];
    }
    __syncthreads();
    #pragma unroll
    for (int j = 0; j < 32; j += 8) {
        size_t idx1 = (size_t)(i0 + threadIdx.y + j) * MATN + j0 + threadIdx.x;
        float v = 0.5f * (ta[threadIdx.y + j][threadIdx.x] + tb[threadIdx.x][threadIdx.y + j]);
        S[idx1] = v;
        __nv_bfloat16 h = __float2bfloat16(v);
        hi[idx1] = h;
        lo[idx1] = __float2bfloat16((v - __bfloat162float(h)) * sc);

        size_t idx2 = (size_t)(j0 + threadIdx.y + j) * MATN + i0 + threadIdx.x;
        float w = 0.5f * (tb[threadIdx.y + j][threadIdx.x] + ta[threadIdx.x][threadIdx.y + j]);
        S[idx2] = w;
        __nv_bfloat16 h2 = __float2bfloat16(w);
        hi[idx2] = h2;
        lo[idx2] = __float2bfloat16((w - __bfloat162float(h2)) * sc);
    }
}

__global__ void k_resid(const float* __restrict__ S, float* __restrict__ part) {
    __shared__ float sm[256];
    float acc = 0.f;
    if (!g_flagL) {
        for (size_t i = (size_t)blockIdx.x * blockDim.x + threadIdx.x; i < NSQL;
             i += (size_t)gridDim.x * blockDim.x) {
            float d = S[i] - ((i / MATN == i % MATN) ? 1.f : 0.f);
            acc = fmaf(d, d, acc);
        }
    }
    sm[threadIdx.x] = acc; __syncthreads();
    for (int s = 128; s > 0; s >>= 1) {
        if (threadIdx.x < s) sm[threadIdx.x] += sm[threadIdx.x + s];
        __syncthreads();
    }
    if (threadIdx.x == 0) part[blockIdx.x] = sm[0];
}
__global__ void k_detect(const float* __restrict__ part) {
    if (g_flagL) return;
    __shared__ float sm[256];
    sm[threadIdx.x] = part[threadIdx.x]; __syncthreads();
    for (int s = 128; s > 0; s >>= 1) {
        if (threadIdx.x < s) sm[threadIdx.x] += sm[threadIdx.x + s];
        __syncthreads();
    }
    if (threadIdx.x == 0 && sm[0] < 0.01f) g_flag = 1;
}

// ---------------- driver ----------------
extern "C" void kernel_launch(void* const* d_in, const int* in_sizes, int n_in,
                              void* d_out, int out_size)
{
    const float* H = (const float*)d_in[0];
    float* out = (float*)d_out;

    float *X0, *X1, *S, *P, *v, *y, *part, *scal;
    __nv_bfloat16 *hA, *lA, *hAT, *lAT, *hS, *lS, *hP, *lP;
    cudaGetSymbolAddress((void**)&X0, g_X0);   cudaGetSymbolAddress((void**)&X1, g_X1);
    cudaGetSymbolAddress((void**)&S, g_S);     cudaGetSymbolAddress((void**)&P, g_P);
    cudaGetSymbolAddress((void**)&hA, g_hA);   cudaGetSymbolAddress((void**)&lA, g_lA);
    cudaGetSymbolAddress((void**)&hAT, g_hAT); cudaGetSymbolAddress((void**)&lAT, g_lAT);
    cudaGetSymbolAddress((void**)&hS, g_hS);   cudaGetSymbolAddress((void**)&lS, g_lS);
    cudaGetSymbolAddress((void**)&hP, g_hP);   cudaGetSymbolAddress((void**)&lP, g_lP);
    cudaGetSymbolAddress((void**)&v, g_v);     cudaGetSymbolAddress((void**)&y, g_y);
    cudaGetSymbolAddress((void**)&part, g_part); cudaGetSymbolAddress((void**)&scal, g_scal);

    cudaFuncSetAttribute(mma_gemm<0>, cudaFuncAttributeMaxDynamicSharedMemorySize, SMEM_SZ);
    cudaFuncSetAttribute(mma_gemm<1>, cudaFuncAttributeMaxDynamicSharedMemorySize, SMEM_SZ);

    k_reset<<<1, 1>>>();

    // --- spectral norm estimate: 10 power iterations, Rayleigh lower bound ---
    k_initv<<<(MATN + 255) / 256, 256>>>(v);
    for (int t = 0; t < 10; ++t) {
        k_sumsq<<<256, 256>>>(v, MATN, part);
        k_finish<<<1, 256>>>(part, scal + 2);
        k_normalize<<<(MATN + 255) / 256, 256>>>(v, scal + 2);
        k_mvn<<<MATN, 128>>>(H, v, y);
        k_mvt<<<MATN / 32, 256>>>(H, y, v);
    }
    k_sumsq<<<256, 256>>>(v, MATN, part);
    k_finish<<<1, 256>>>(part, scal + 2);
    k_normalize<<<(MATN + 255) / 256, 256>>>(v, scal + 2);
    k_mvn<<<MATN, 128>>>(H, v, y);
    k_sumsq<<<256, 256>>>(y, MATN, part);
    k_finish<<<1, 256>>>(part, scal + 1);   // scal[1] = sigma_ray^2

    // --- schedule: 1 x L125, 8 x LA, 1 x COMP, 2 x NS  (12 steps) ---
    const int NSTEP = 12;
    float ca[NSTEP], cb[NSTEP], cc[NSTEP];
    for (int i = 0; i < NSTEP; ++i) {
        if (i == 0)      { ca[i] = 3.140664f;  cb[i] = -5.165150f;  cc[i] = 2.346307f; }
        else if (i <= 8) { ca[i] = 3.9258326f; cb[i] = -10.0881832f; cc[i] = 7.1603506f; }
        else if (i == 9) { ca[i] = 2.8426f;    cb[i] = -4.4442f;    cc[i] = 2.6015f; }
        else             { ca[i] = 1.875f;     cb[i] = -1.25f;      cc[i] = 0.375f; }
    }

    dim3 grd(MATN / 128, MATN / 256);   // (32, 16)
    dim3 g32(MATN / 32, MATN / 32);
    dim3 b32(32, 8);
    float* Xc = X0;
    float* Xn = X1;

    for (int st = 0; st < NSTEP; ++st) {
        float* dst = (st == NSTEP - 1) ? out : Xn;
        const float a = ca[st], b = cb[st], c = cc[st];

        k_latch<<<1, 1>>>();
        k_copy_if<<<1024, 256>>>((st == 0) ? X0 : Xc, dst);

        k_splitT<<<g32, b32>>>((st == 0) ? H : Xc, hA, lA, hAT, lAT, 2.0f, (st == 0) ? 1 : 0);

        // S = sym( hAT*hAT^T + hAT*(2 lAT)^T )
        mma_gemm<0><<<grd, 256, SMEM_SZ>>>(hAT, hAT, hAT, lAT, hAT, hAT, 2, S, nullptr, 0, 0, 0);
        k_symsplit<<<g32, b32>>>(S, hS, lS, 2.0f);

        k_resid<<<256, 256>>>(S, part);
        k_detect<<<1, 256>>>(part);

        // P = sym( c*(Sh*Sh + 2*Sh*Sl) + b*S + a*I )
        mma_gemm<1><<<grd, 256, SMEM_SZ>>>(hS, hS, hS, lS, hS, hS, 2, P, S, a, b, c);
        k_symsplit<<<g32, b32>>>(P, hP, lP, 1.0f);

        // X' = Xh*Ph + Xh*Pl + Xl*Ph
        mma_gemm<0><<<grd, 256, SMEM_SZ>>>(hA, hP, hA, lP, lA, hP, 3, dst, nullptr, 0, 0, 0);

        float* t = Xc; Xc = Xn; Xn = t;
        if (st == 0) Xc = X1;
    }
}

// round 8
// speedup vs baseline: 1.3767x; 1.3767x over previous
#include <cuda_runtime.h>
#include <cuda_fp16.h>
#include <cstdint>
#include <math.h>

#define MATN 4096
#define NSQL ((size_t)MATN * (size_t)MATN)

// ---------------- static device scratch ----------------
__device__ float g_X0[MATN * MATN];
__device__ float g_X1[MATN * MATN];
__device__ float g_S [MATN * MATN];
__device__ float g_P [MATN * MATN];
__device__ __half g_hA [MATN * MATN];
__device__ __half g_lA [MATN * MATN];
__device__ __half g_hAT[MATN * MATN];
__device__ __half g_lAT[MATN * MATN];
__device__ __half g_hS [MATN * MATN];
__device__ __half g_lS [MATN * MATN];
__device__ __half g_hP [MATN * MATN];
__device__ __half g_lP [MATN * MATN];
__device__ float g_v[MATN];
__device__ float g_y[MATN];
__device__ float g_part[256];
__device__ float g_scal[4];    // [1]=sigma_ray^2  [2]=tmp norm
__device__ int   g_flag;
__device__ int   g_flagL;

// ---------------- helpers ----------------
__device__ __forceinline__ uint32_t smem_u32(const void* p) {
    uint32_t a;
    asm("{ .reg .u64 t; cvta.to.shared.u64 t, %1; cvt.u32.u64 %0, t; }" : "=r"(a) : "l"(p));
    return a;
}
__device__ __forceinline__ void cp16(uint32_t dst, const void* src) {
    asm volatile("cp.async.cg.shared.global [%0], [%1], 16;" :: "r"(dst), "l"(src));
}
#define CP_COMMIT() asm volatile("cp.async.commit_group;" ::: "memory")
#define CP_WAIT(N)  asm volatile("cp.async.wait_group %0;" :: "n"(N) : "memory")

#define LDSM_X4(r, a)                                                           \
    asm volatile("ldmatrix.sync.aligned.m8n8.x4.shared.b16 {%0,%1,%2,%3}, [%4];" \
        : "=r"((r)[0]), "=r"((r)[1]), "=r"((r)[2]), "=r"((r)[3]) : "r"(a))

__device__ __forceinline__ void mma_f16(float* d, const uint32_t* a,
                                        uint32_t b0, uint32_t b1) {
    asm volatile(
        "mma.sync.aligned.m16n8k16.row.col.f32.f16.f16.f32 "
        "{%0,%1,%2,%3}, {%4,%5,%6,%7}, {%8,%9}, {%0,%1,%2,%3};"
        : "+f"(d[0]), "+f"(d[1]), "+f"(d[2]), "+f"(d[3])
        : "r"(a[0]), "r"(a[1]), "r"(a[2]), "r"(a[3]), "r"(b0), "r"(b1));
}

// ---------------- fp16 tensor-core GEMM (mma.sync) ----------------
// C = sum_s A_s * B_s^T ; POLY=1: C = c2*D + c1*E + c0*I.
// TRI=1: compute only tiles with col-tile >= row-tile (upper triangle).
// Tile 128x128, BK=32, 256 thr (8 warps: 4 row x 2 col, 32x64 each), 2-stage.
#define BROW 80
#define ABYTES (128 * BROW)
#define BUFBYTES (2 * ABYTES)

template<int POLY, int TRI>
__global__ void __launch_bounds__(256, 2)
mma_gemm(const __half* __restrict__ A0, const __half* __restrict__ B0,
         const __half* __restrict__ A1, const __half* __restrict__ B1,
         const __half* __restrict__ A2, const __half* __restrict__ B2,
         int nseg, float* __restrict__ C, const float* __restrict__ E,
         float c0, float c1, float c2)
{
    if (g_flagL) return;
    if (TRI && (int)blockIdx.x < (int)blockIdx.y) return;
    __shared__ __align__(16) char smem[2 * BUFBYTES];
    const uint32_t sbase = smem_u32(smem);

    const int tid  = threadIdx.x;
    const int wid  = tid >> 5, lane = tid & 31;
    const int wr   = wid & 3;
    const int wc   = wid >> 2;
    const int row0 = blockIdx.y * 128;
    const int col0 = blockIdx.x * 128;

    const __half* Aseg[3] = {A0, A1, A2};
    const __half* Bseg[3] = {B0, B1, B2};

    float acc[2][8][4];
    #pragma unroll
    for (int i = 0; i < 2; ++i)
        #pragma unroll
        for (int j = 0; j < 8; ++j)
            #pragma unroll
            for (int k = 0; k < 4; ++k) acc[i][j][k] = 0.f;

    auto load_chunk = [&](int ch, int buf) {
        const int seg = ch >> 7, kc = ch & 127;
        const __half* Ap = Aseg[seg] + (size_t)row0 * MATN + kc * 32;
        const __half* Bp = Bseg[seg] + (size_t)col0 * MATN + kc * 32;
        const uint32_t sa = sbase + buf * BUFBYTES;
        const uint32_t sb = sa + ABYTES;
        #pragma unroll
        for (int p = 0; p < 2; ++p) {
            int q = tid + p * 256;
            int r = q >> 2, s = q & 3;
            cp16(sa + r * BROW + s * 16, Ap + (size_t)r * MATN + s * 8);
            cp16(sb + r * BROW + s * 16, Bp + (size_t)r * MATN + s * 8);
        }
        CP_COMMIT();
    };

    const int total = nseg * 128;
    load_chunk(0, 0);

    for (int ch = 0; ch < total; ++ch) {
        const int buf = ch & 1;
        if (ch + 1 < total) { load_chunk(ch + 1, buf ^ 1); CP_WAIT(1); }
        else                { CP_WAIT(0); }
        __syncthreads();

        const uint32_t sa = sbase + buf * BUFBYTES;
        const uint32_t sb = sa + ABYTES;
        #pragma unroll
        for (int kk = 0; kk < 2; ++kk) {
            uint32_t af[2][4], bf[4][4];
            #pragma unroll
            for (int mt = 0; mt < 2; ++mt) {
                uint32_t addr = sa + (uint32_t)(wr * 32 + mt * 16 + (lane & 15)) * BROW
                              + kk * 32 + (lane >> 4) * 16;
                LDSM_X4(af[mt], addr);
            }
            #pragma unroll
            for (int bp = 0; bp < 4; ++bp) {
                int grp = lane >> 3, wi = lane & 7;
                uint32_t addr = sb + (uint32_t)(wc * 64 + bp * 16 + wi + (grp >> 1) * 8) * BROW
                              + kk * 32 + (grp & 1) * 16;
                LDSM_X4(bf[bp], addr);
            }
            #pragma unroll
            for (int mt = 0; mt < 2; ++mt)
                #pragma unroll
                for (int nt = 0; nt < 8; ++nt)
                    mma_f16(acc[mt][nt], af[mt], bf[nt >> 1][(nt & 1) * 2],
                            bf[nt >> 1][(nt & 1) * 2 + 1]);
        }
        __syncthreads();
    }

    #pragma unroll
    for (int mt = 0; mt < 2; ++mt) {
        #pragma unroll
        for (int half = 0; half < 2; ++half) {
            const int rg = row0 + wr * 32 + mt * 16 + (lane >> 2) + half * 8;
            const size_t rowbase = (size_t)rg * MATN;
            #pragma unroll
            for (int nt = 0; nt < 8; ++nt) {
                const int cc = col0 + wc * 64 + nt * 8 + (lane & 3) * 2;
                float v0 = acc[mt][nt][half * 2 + 0];
                float v1 = acc[mt][nt][half * 2 + 1];
                if (POLY) {
                    float2 e = *reinterpret_cast<const float2*>(E + rowbase + cc);
                    v0 = c2 * v0 + c1 * e.x + ((rg == cc)     ? c0 : 0.f);
                    v1 = c2 * v1 + c1 * e.y + ((rg == cc + 1) ? c0 : 0.f);
                }
                float2 o = make_float2(v0, v1);
                *reinterpret_cast<float2*>(C + rowbase + cc) = o;
            }
        }
    }
}

// ---------------- small kernels ----------------
__global__ void k_reset() { g_flag = 0; g_flagL = 0; }
__global__ void k_latch() { g_flagL = g_flag; }

__global__ void k_copy_if(const float* __restrict__ src, float* __restrict__ dst) {
    if (!g_flagL) return;
    for (size_t i = (size_t)blockIdx.x * blockDim.x + threadIdx.x; i < NSQL / 4;
         i += (size_t)gridDim.x * blockDim.x)
        reinterpret_cast<float4*>(dst)[i] = reinterpret_cast<const float4*>(src)[i];
}

__global__ void k_sumsq(const float* __restrict__ x, int n, float* __restrict__ part) {
    __shared__ float sm[256];
    float acc = 0.f;
    for (int i = blockIdx.x * blockDim.x + threadIdx.x; i < n; i += gridDim.x * blockDim.x) {
        float v = x[i]; acc = fmaf(v, v, acc);
    }
    sm[threadIdx.x] = acc; __syncthreads();
    for (int s = 128; s > 0; s >>= 1) {
        if (threadIdx.x < s) sm[threadIdx.x] += sm[threadIdx.x + s];
        __syncthreads();
    }
    if (threadIdx.x == 0) part[blockIdx.x] = sm[0];
}
__global__ void k_finish(const float* __restrict__ part, float* __restrict__ dst) {
    __shared__ float sm[256];
    sm[threadIdx.x] = part[threadIdx.x]; __syncthreads();
    for (int s = 128; s > 0; s >>= 1) {
        if (threadIdx.x < s) sm[threadIdx.x] += sm[threadIdx.x + s];
        __syncthreads();
    }
    if (threadIdx.x == 0) *dst = sm[0];
}

__global__ void k_initv(float* v) {
    int j = blockIdx.x * blockDim.x + threadIdx.x;
    if (j < MATN) {
        unsigned h = (unsigned)j * 2654435761u;
        h ^= h >> 13; h *= 0x5bd1e995u; h ^= h >> 15;
        v[j] = ((float)(h & 0xFFFFu) / 65536.0f) - 0.5f + 0.001f;
    }
}
__global__ void k_normalize(float* v, const float* n2) {
    int j = blockIdx.x * blockDim.x + threadIdx.x;
    float s = rsqrtf(*n2 + 1e-30f);
    if (j < MATN) v[j] *= s;
}
__global__ void k_mvn(const float* __restrict__ H, const float* __restrict__ v,
                      float* __restrict__ y) {
    __shared__ float sm[128];
    int r = blockIdx.x;
    const float* row = H + (size_t)r * MATN;
    float acc = 0.f;
    for (int j = threadIdx.x; j < MATN; j += 128) acc = fmaf(row[j], v[j], acc);
    sm[threadIdx.x] = acc; __syncthreads();
    for (int s = 64; s > 0; s >>= 1) {
        if (threadIdx.x < s) sm[threadIdx.x] += sm[threadIdx.x + s];
        __syncthreads();
    }
    if (threadIdx.x == 0) y[r] = sm[0];
}
__global__ void k_mvt(const float* __restrict__ H, const float* __restrict__ y,
                      float* __restrict__ z) {
    __shared__ float sm[256];
    int tj = threadIdx.x & 31, gi = threadIdx.x >> 5;
    int j = blockIdx.x * 32 + tj;
    float acc = 0.f;
    for (int i = gi * 512; i < gi * 512 + 512; ++i)
        acc = fmaf(H[(size_t)i * MATN + j], y[i], acc);
    sm[threadIdx.x] = acc; __syncthreads();
    if (threadIdx.x < 32) {
        float t = 0.f;
        #pragma unroll
        for (int g = 0; g < 8; ++g) t += sm[threadIdx.x + 32 * g];
        z[j] = t;
    }
}

// split X -> (hi, lo) and transposed copies; optional prescale from g_scal[1]
__global__ void k_splitT(const float* __restrict__ X,
                         __half* __restrict__ hi, __half* __restrict__ lo,
                         __half* __restrict__ hiT, __half* __restrict__ loT,
                         int prescale) {
    if (g_flagL) return;
    __shared__ float t[32][33];
    float s = prescale ? (rsqrtf(g_scal[1] + 1e-30f) / 1.10f) : 1.0f;
    int x0 = blockIdx.x * 32, y0 = blockIdx.y * 32;
    #pragma unroll
    for (int j = 0; j < 32; j += 8) {
        int r = y0 + threadIdx.y + j, c = x0 + threadIdx.x;
        float v = X[(size_t)r * MATN + c] * s;
        t[threadIdx.y + j][threadIdx.x] = v;
        __half h = __float2half(v);
        hi[(size_t)r * MATN + c] = h;
        lo[(size_t)r * MATN + c] = __float2half(v - __half2float(h));
    }
    __syncthreads();
    #pragma unroll
    for (int j = 0; j < 32; j += 8) {
        int r = x0 + threadIdx.y + j, c = y0 + threadIdx.x;
        float v = t[threadIdx.x][threadIdx.y + j];
        __half h = __float2half(v);
        hiT[(size_t)r * MATN + c] = h;
        loT[(size_t)r * MATN + c] = __float2half(v - __half2float(h));
    }
}

// read upper tile of S (bj>=bi), split to hi/lo at (i,j) AND mirrored (j,i);
// also mirror the fp32 value into the lower triangle. Diagonal tiles: no mirror.
__global__ void k_mirsplit(float* __restrict__ S,
                           __half* __restrict__ hi, __half* __restrict__ lo) {
    if (g_flagL) return;
    __shared__ float ta[32][33];
    int bi = blockIdx.y, bj = blockIdx.x;
    if (bj < bi) return;
    int i0 = bi * 32, j0 = bj * 32;
    #pragma unroll
    for (int j = 0; j < 32; j += 8) {
        size_t idx1 = (size_t)(i0 + threadIdx.y + j) * MATN + j0 + threadIdx.x;
        float v = S[idx1];
        ta[threadIdx.y + j][threadIdx.x] = v;
        __half h = __float2half(v);
        hi[idx1] = h;
        lo[idx1] = __float2half(v - __half2float(h));
    }
    if (bi == bj) return;
    __syncthreads();
    #pragma unroll
    for (int j = 0; j < 32; j += 8) {
        // write transposed tile at (j0, i0)
        size_t idx2 = (size_t)(j0 + threadIdx.y + j) * MATN + i0 + threadIdx.x;
        float v = ta[threadIdx.x][threadIdx.y + j];
        S[idx2] = v;
        __half h = __float2half(v);
        hi[idx2] = h;
        lo[idx2] = __float2half(v - __half2float(h));
    }
}

__global__ void k_resid(const float* __restrict__ S, float* __restrict__ part) {
    __shared__ float sm[256];
    float acc = 0.f;
    if (!g_flagL) {
        for (size_t i = (size_t)blockIdx.x * blockDim.x + threadIdx.x; i < NSQL;
             i += (size_t)gridDim.x * blockDim.x) {
            float d = S[i] - ((i / MATN == i % MATN) ? 1.f : 0.f);
            acc = fmaf(d, d, acc);
        }
    }
    sm[threadIdx.x] = acc; __syncthreads();
    for (int s = 128; s > 0; s >>= 1) {
        if (threadIdx.x < s) sm[threadIdx.x] += sm[threadIdx.x + s];
        __syncthreads();
    }
    if (threadIdx.x == 0) part[blockIdx.x] = sm[0];
}
__global__ void k_detect(const float* __restrict__ part) {
    if (g_flagL) return;
    __shared__ float sm[256];
    sm[threadIdx.x] = part[threadIdx.x]; __syncthreads();
    for (int s = 128; s > 0; s >>= 1) {
        if (threadIdx.x < s) sm[threadIdx.x] += sm[threadIdx.x + s];
        __syncthreads();
    }
    if (threadIdx.x == 0 && sm[0] < 0.01f) g_flag = 1;
}

// ---------------- driver ----------------
extern "C" void kernel_launch(void* const* d_in, const int* in_sizes, int n_in,
                              void* d_out, int out_size)
{
    const float* H = (const float*)d_in[0];
    float* out = (float*)d_out;

    float *X0, *X1, *S, *P, *v, *y, *part, *scal;
    __half *hA, *lA, *hAT, *lAT, *hS, *lS, *hP, *lP;
    cudaGetSymbolAddress((void**)&X0, g_X0);   cudaGetSymbolAddress((void**)&X1, g_X1);
    cudaGetSymbolAddress((void**)&S, g_S);     cudaGetSymbolAddress((void**)&P, g_P);
    cudaGetSymbolAddress((void**)&hA, g_hA);   cudaGetSymbolAddress((void**)&lA, g_lA);
    cudaGetSymbolAddress((void**)&hAT, g_hAT); cudaGetSymbolAddress((void**)&lAT, g_lAT);
    cudaGetSymbolAddress((void**)&hS, g_hS);   cudaGetSymbolAddress((void**)&lS, g_lS);
    cudaGetSymbolAddress((void**)&hP, g_hP);   cudaGetSymbolAddress((void**)&lP, g_lP);
    cudaGetSymbolAddress((void**)&v, g_v);     cudaGetSymbolAddress((void**)&y, g_y);
    cudaGetSymbolAddress((void**)&part, g_part); cudaGetSymbolAddress((void**)&scal, g_scal);

    k_reset<<<1, 1>>>();

    // --- spectral norm estimate: 10 power iterations, Rayleigh lower bound ---
    k_initv<<<(MATN + 255) / 256, 256>>>(v);
    for (int t = 0; t < 10; ++t) {
        k_sumsq<<<256, 256>>>(v, MATN, part);
        k_finish<<<1, 256>>>(part, scal + 2);
        k_normalize<<<(MATN + 255) / 256, 256>>>(v, scal + 2);
        k_mvn<<<MATN, 128>>>(H, v, y);
        k_mvt<<<MATN / 32, 256>>>(H, y, v);
    }
    k_sumsq<<<256, 256>>>(v, MATN, part);
    k_finish<<<1, 256>>>(part, scal + 2);
    k_normalize<<<(MATN + 255) / 256, 256>>>(v, scal + 2);
    k_mvn<<<MATN, 128>>>(H, v, y);
    k_sumsq<<<256, 256>>>(y, MATN, part);
    k_finish<<<1, 256>>>(part, scal + 1);   // scal[1] = sigma_ray^2

    // --- schedule: 1 x L125, 8 x LA, 1 x COMP, 2 x NS  (12 steps) ---
    const int NSTEP = 12;
    float ca[NSTEP], cb[NSTEP], cc[NSTEP];
    for (int i = 0; i < NSTEP; ++i) {
        if (i == 0)      { ca[i] = 3.140664f;  cb[i] = -5.165150f;  cc[i] = 2.346307f; }
        else if (i <= 8) { ca[i] = 3.9258326f; cb[i] = -10.0881832f; cc[i] = 7.1603506f; }
        else if (i == 9) { ca[i] = 2.8426f;    cb[i] = -4.4442f;    cc[i] = 2.6015f; }
        else             { ca[i] = 1.875f;     cb[i] = -1.25f;      cc[i] = 0.375f; }
    }

    dim3 grd(MATN / 128, MATN / 128);   // (32, 32)
    dim3 g32(MATN / 32, MATN / 32);
    dim3 b32(32, 8);
    float* Xc = X0;
    float* Xn = X1;

    for (int st = 0; st < NSTEP; ++st) {
        float* dst = (st == NSTEP - 1) ? out : Xn;
        const float a = ca[st], b = cb[st], c = cc[st];

        k_latch<<<1, 1>>>();
        k_copy_if<<<1024, 256>>>((st == 0) ? X0 : Xc, dst);

        k_splitT<<<g32, b32>>>((st == 0) ? H : Xc, hA, lA, hAT, lAT, (st == 0) ? 1 : 0);

        // S = X^T X  (upper tiles): hh + hl + lh  per tile -> exact split value
        mma_gemm<0, 1><<<grd, 256>>>(hAT, hAT, hAT, lAT, lAT, hAT, 3, S, nullptr, 0, 0, 0);
        k_mirsplit<<<g32, b32>>>(S, hS, lS);

        k_resid<<<256, 256>>>(S, part);
        k_detect<<<1, 256>>>(part);

        // P = a I + b S + c S^2  (upper tiles)
        mma_gemm<1, 1><<<grd, 256>>>(hS, hS, hS, lS, lS, hS, 3, P, S, a, b, c);
        k_mirsplit<<<g32, b32>>>(P, hP, lP);

        // X' = Xh*Ph + Xh*Pl + Xl*Ph   (full grid; P symmetric)
        mma_gemm<0, 0><<<grd, 256>>>(hA, hP, hA, lP, lA, hP, 3, dst, nullptr, 0, 0, 0);

        float* t = Xc; Xc = Xn; Xn = t;
        if (st == 0) Xc = X1;
    }
}

// round 9
// speedup vs baseline: 2.0375x; 1.4800x over previous
#include <cuda_runtime.h>
#include <cuda_fp16.h>
#include <cstdint>
#include <math.h>

#define MATN 4096
#define NSQL ((size_t)MATN * (size_t)MATN)

// ---------------- static device scratch ----------------
__device__ float g_X0[MATN * MATN];
__device__ float g_X1[MATN * MATN];
__device__ float g_S [MATN * MATN];
__device__ float g_P [MATN * MATN];
__device__ __half g_hA [MATN * MATN];
__device__ __half g_lA [MATN * MATN];
__device__ __half g_hAT[MATN * MATN];
__device__ __half g_lAT[MATN * MATN];
__device__ __half g_hS [MATN * MATN];
__device__ __half g_lS [MATN * MATN];
__device__ __half g_hP [MATN * MATN];
__device__ __half g_lP [MATN * MATN];
__device__ float g_v[MATN];
__device__ float g_y[MATN];
__device__ float g_part[256];
__device__ float g_scal[4];    // [1]=sigma_ray^2  [2]=tmp norm
__device__ int   g_flag;
__device__ int   g_flagL;

// ---------------- helpers ----------------
__device__ __forceinline__ uint32_t smem_u32(const void* p) {
    uint32_t a;
    asm("{ .reg .u64 t; cvta.to.shared.u64 t, %1; cvt.u32.u64 %0, t; }" : "=r"(a) : "l"(p));
    return a;
}
__device__ __forceinline__ void cp16(uint32_t dst, const void* src) {
    asm volatile("cp.async.cg.shared.global [%0], [%1], 16;" :: "r"(dst), "l"(src));
}
#define CP_COMMIT() asm volatile("cp.async.commit_group;" ::: "memory")
#define CP_WAIT(N)  asm volatile("cp.async.wait_group %0;" :: "n"(N) : "memory")

#define LDSM_X4(r, a)                                                           \
    asm volatile("ldmatrix.sync.aligned.m8n8.x4.shared.b16 {%0,%1,%2,%3}, [%4];" \
        : "=r"((r)[0]), "=r"((r)[1]), "=r"((r)[2]), "=r"((r)[3]) : "r"(a))

__device__ __forceinline__ void mma_f16(float* d, const uint32_t* a,
                                        uint32_t b0, uint32_t b1) {
    asm volatile(
        "mma.sync.aligned.m16n8k16.row.col.f32.f16.f16.f32 "
        "{%0,%1,%2,%3}, {%4,%5,%6,%7}, {%8,%9}, {%0,%1,%2,%3};"
        : "+f"(d[0]), "+f"(d[1]), "+f"(d[2]), "+f"(d[3])
        : "r"(a[0]), "r"(a[1]), "r"(a[2]), "r"(a[3]), "r"(b0), "r"(b1));
}

// ---------------- fp16 tensor-core GEMM (mma.sync) ----------------
// C = sum_s A_s * B_s^T ; POLY=1: C = c2*D + c1*E + c0*I.
// TRI=1: compute only tiles with col-tile >= row-tile (upper triangle).
#define BROW 80
#define ABYTES (128 * BROW)
#define BUFBYTES (2 * ABYTES)

template<int POLY, int TRI>
__global__ void __launch_bounds__(256, 2)
mma_gemm(const __half* __restrict__ A0, const __half* __restrict__ B0,
         const __half* __restrict__ A1, const __half* __restrict__ B1,
         const __half* __restrict__ A2, const __half* __restrict__ B2,
         int nseg, float* __restrict__ C, const float* __restrict__ E,
         float c0, float c1, float c2)
{
    if (g_flagL) return;
    if (TRI && (int)blockIdx.x < (int)blockIdx.y) return;
    __shared__ __align__(16) char smem[2 * BUFBYTES];
    const uint32_t sbase = smem_u32(smem);

    const int tid  = threadIdx.x;
    const int wid  = tid >> 5, lane = tid & 31;
    const int wr   = wid & 3;
    const int wc   = wid >> 2;
    const int row0 = blockIdx.y * 128;
    const int col0 = blockIdx.x * 128;

    const __half* Aseg[3] = {A0, A1, A2};
    const __half* Bseg[3] = {B0, B1, B2};

    float acc[2][8][4];
    #pragma unroll
    for (int i = 0; i < 2; ++i)
        #pragma unroll
        for (int j = 0; j < 8; ++j)
            #pragma unroll
            for (int k = 0; k < 4; ++k) acc[i][j][k] = 0.f;

    auto load_chunk = [&](int ch, int buf) {
        const int seg = ch >> 7, kc = ch & 127;
        const __half* Ap = Aseg[seg] + (size_t)row0 * MATN + kc * 32;
        const __half* Bp = Bseg[seg] + (size_t)col0 * MATN + kc * 32;
        const uint32_t sa = sbase + buf * BUFBYTES;
        const uint32_t sb = sa + ABYTES;
        #pragma unroll
        for (int p = 0; p < 2; ++p) {
            int q = tid + p * 256;
            int r = q >> 2, s = q & 3;
            cp16(sa + r * BROW + s * 16, Ap + (size_t)r * MATN + s * 8);
            cp16(sb + r * BROW + s * 16, Bp + (size_t)r * MATN + s * 8);
        }
        CP_COMMIT();
    };

    const int total = nseg * 128;
    load_chunk(0, 0);

    for (int ch = 0; ch < total; ++ch) {
        const int buf = ch & 1;
        if (ch + 1 < total) { load_chunk(ch + 1, buf ^ 1); CP_WAIT(1); }
        else                { CP_WAIT(0); }
        __syncthreads();

        const uint32_t sa = sbase + buf * BUFBYTES;
        const uint32_t sb = sa + ABYTES;
        #pragma unroll
        for (int kk = 0; kk < 2; ++kk) {
            uint32_t af[2][4], bf[4][4];
            #pragma unroll
            for (int mt = 0; mt < 2; ++mt) {
                uint32_t addr = sa + (uint32_t)(wr * 32 + mt * 16 + (lane & 15)) * BROW
                              + kk * 32 + (lane >> 4) * 16;
                LDSM_X4(af[mt], addr);
            }
            #pragma unroll
            for (int bp = 0; bp < 4; ++bp) {
                int grp = lane >> 3, wi = lane & 7;
                uint32_t addr = sb + (uint32_t)(wc * 64 + bp * 16 + wi + (grp >> 1) * 8) * BROW
                              + kk * 32 + (grp & 1) * 16;
                LDSM_X4(bf[bp], addr);
            }
            #pragma unroll
            for (int mt = 0; mt < 2; ++mt)
                #pragma unroll
                for (int nt = 0; nt < 8; ++nt)
                    mma_f16(acc[mt][nt], af[mt], bf[nt >> 1][(nt & 1) * 2],
                            bf[nt >> 1][(nt & 1) * 2 + 1]);
        }
        __syncthreads();
    }

    #pragma unroll
    for (int mt = 0; mt < 2; ++mt) {
        #pragma unroll
        for (int half = 0; half < 2; ++half) {
            const int rg = row0 + wr * 32 + mt * 16 + (lane >> 2) + half * 8;
            const size_t rowbase = (size_t)rg * MATN;
            #pragma unroll
            for (int nt = 0; nt < 8; ++nt) {
                const int cc = col0 + wc * 64 + nt * 8 + (lane & 3) * 2;
                float v0 = acc[mt][nt][half * 2 + 0];
                float v1 = acc[mt][nt][half * 2 + 1];
                if (POLY) {
                    float2 e = *reinterpret_cast<const float2*>(E + rowbase + cc);
                    v0 = c2 * v0 + c1 * e.x + ((rg == cc)     ? c0 : 0.f);
                    v1 = c2 * v1 + c1 * e.y + ((rg == cc + 1) ? c0 : 0.f);
                }
                float2 o = make_float2(v0, v1);
                *reinterpret_cast<float2*>(C + rowbase + cc) = o;
            }
        }
    }
}

// ---------------- small kernels ----------------
__global__ void k_reset() { g_flag = 0; g_flagL = 0; }
__global__ void k_latch() { g_flagL = g_flag; }

__global__ void k_copy_if(const float* __restrict__ src, float* __restrict__ dst) {
    if (!g_flagL) return;
    for (size_t i = (size_t)blockIdx.x * blockDim.x + threadIdx.x; i < NSQL / 4;
         i += (size_t)gridDim.x * blockDim.x)
        reinterpret_cast<float4*>(dst)[i] = reinterpret_cast<const float4*>(src)[i];
}

__global__ void k_sumsq(const float* __restrict__ x, int n, float* __restrict__ part) {
    __shared__ float sm[256];
    float acc = 0.f;
    for (int i = blockIdx.x * blockDim.x + threadIdx.x; i < n; i += gridDim.x * blockDim.x) {
        float v = x[i]; acc = fmaf(v, v, acc);
    }
    sm[threadIdx.x] = acc; __syncthreads();
    for (int s = 128; s > 0; s >>= 1) {
        if (threadIdx.x < s) sm[threadIdx.x] += sm[threadIdx.x + s];
        __syncthreads();
    }
    if (threadIdx.x == 0) part[blockIdx.x] = sm[0];
}
__global__ void k_finish(const float* __restrict__ part, float* __restrict__ dst) {
    __shared__ float sm[256];
    sm[threadIdx.x] = part[threadIdx.x]; __syncthreads();
    for (int s = 128; s > 0; s >>= 1) {
        if (threadIdx.x < s) sm[threadIdx.x] += sm[threadIdx.x + s];
        __syncthreads();
    }
    if (threadIdx.x == 0) *dst = sm[0];
}

__global__ void k_initv(float* v) {
    int j = blockIdx.x * blockDim.x + threadIdx.x;
    if (j < MATN) {
        unsigned h = (unsigned)j * 2654435761u;
        h ^= h >> 13; h *= 0x5bd1e995u; h ^= h >> 15;
        v[j] = ((float)(h & 0xFFFFu) / 65536.0f) - 0.5f + 0.001f;
    }
}
__global__ void k_normalize(float* v, const float* n2) {
    int j = blockIdx.x * blockDim.x + threadIdx.x;
    float s = rsqrtf(*n2 + 1e-30f);
    if (j < MATN) v[j] *= s;
}
__global__ void k_mvn(const float* __restrict__ H, const float* __restrict__ v,
                      float* __restrict__ y) {
    __shared__ float sm[128];
    int r = blockIdx.x;
    const float* row = H + (size_t)r * MATN;
    float acc = 0.f;
    for (int j = threadIdx.x; j < MATN; j += 128) acc = fmaf(row[j], v[j], acc);
    sm[threadIdx.x] = acc; __syncthreads();
    for (int s = 64; s > 0; s >>= 1) {
        if (threadIdx.x < s) sm[threadIdx.x] += sm[threadIdx.x + s];
        __syncthreads();
    }
    if (threadIdx.x == 0) y[r] = sm[0];
}
__global__ void k_mvt(const float* __restrict__ H, const float* __restrict__ y,
                      float* __restrict__ z) {
    __shared__ float sm[256];
    int tj = threadIdx.x & 31, gi = threadIdx.x >> 5;
    int j = blockIdx.x * 32 + tj;
    float acc = 0.f;
    for (int i = gi * 512; i < gi * 512 + 512; ++i)
        acc = fmaf(H[(size_t)i * MATN + j], y[i], acc);
    sm[threadIdx.x] = acc; __syncthreads();
    if (threadIdx.x < 32) {
        float t = 0.f;
        #pragma unroll
        for (int g = 0; g < 8; ++g) t += sm[threadIdx.x + 32 * g];
        z[j] = t;
    }
}

// split X -> (hi, lo) and transposed copies; optional prescale from g_scal[1]
__global__ void k_splitT(const float* __restrict__ X,
                         __half* __restrict__ hi, __half* __restrict__ lo,
                         __half* __restrict__ hiT, __half* __restrict__ loT,
                         int prescale) {
    if (g_flagL) return;
    __shared__ float t[32][33];
    float s = prescale ? (rsqrtf(g_scal[1] + 1e-30f) / 1.10f) : 1.0f;
    int x0 = blockIdx.x * 32, y0 = blockIdx.y * 32;
    #pragma unroll
    for (int j = 0; j < 32; j += 8) {
        int r = y0 + threadIdx.y + j, c = x0 + threadIdx.x;
        float v = X[(size_t)r * MATN + c] * s;
        t[threadIdx.y + j][threadIdx.x] = v;
        __half h = __float2half(v);
        hi[(size_t)r * MATN + c] = h;
        lo[(size_t)r * MATN + c] = __float2half(v - __half2float(h));
    }
    __syncthreads();
    #pragma unroll
    for (int j = 0; j < 32; j += 8) {
        int r = x0 + threadIdx.y + j, c = y0 + threadIdx.x;
        float v = t[threadIdx.x][threadIdx.y + j];
        __half h = __float2half(v);
        hiT[(size_t)r * MATN + c] = h;
        loT[(size_t)r * MATN + c] = __float2half(v - __half2float(h));
    }
}

// read upper tile of S (bj>=bi), split (hi always, lo if wlo) at (i,j) and mirror (j,i)
__global__ void k_mirsplit(float* __restrict__ S,
                           __half* __restrict__ hi, __half* __restrict__ lo, int wlo) {
    if (g_flagL) return;
    __shared__ float ta[32][33];
    int bi = blockIdx.y, bj = blockIdx.x;
    if (bj < bi) return;
    int i0 = bi * 32, j0 = bj * 32;
    #pragma unroll
    for (int j = 0; j < 32; j += 8) {
        size_t idx1 = (size_t)(i0 + threadIdx.y + j) * MATN + j0 + threadIdx.x;
        float v = S[idx1];
        ta[threadIdx.y + j][threadIdx.x] = v;
        __half h = __float2half(v);
        hi[idx1] = h;
        if (wlo) lo[idx1] = __float2half(v - __half2float(h));
    }
    if (bi == bj) return;
    __syncthreads();
    #pragma unroll
    for (int j = 0; j < 32; j += 8) {
        size_t idx2 = (size_t)(j0 + threadIdx.y + j) * MATN + i0 + threadIdx.x;
        float v = ta[threadIdx.x][threadIdx.y + j];
        S[idx2] = v;
        __half h = __float2half(v);
        hi[idx2] = h;
        if (wlo) lo[idx2] = __float2half(v - __half2float(h));
    }
}

__global__ void k_resid(const float* __restrict__ S, float* __restrict__ part) {
    __shared__ float sm[256];
    float acc = 0.f;
    if (!g_flagL) {
        for (size_t i = (size_t)blockIdx.x * blockDim.x + threadIdx.x; i < NSQL;
             i += (size_t)gridDim.x * blockDim.x) {
            float d = S[i] - ((i / MATN == i % MATN) ? 1.f : 0.f);
            acc = fmaf(d, d, acc);
        }
    }
    sm[threadIdx.x] = acc; __syncthreads();
    for (int s = 128; s > 0; s >>= 1) {
        if (threadIdx.x < s) sm[threadIdx.x] += sm[threadIdx.x + s];
        __syncthreads();
    }
    if (threadIdx.x == 0) part[blockIdx.x] = sm[0];
}
__global__ void k_detect(const float* __restrict__ part) {
    if (g_flagL) return;
    __shared__ float sm[256];
    sm[threadIdx.x] = part[threadIdx.x]; __syncthreads();
    for (int s = 128; s > 0; s >>= 1) {
        if (threadIdx.x < s) sm[threadIdx.x] += sm[threadIdx.x + s];
        __syncthreads();
    }
    if (threadIdx.x == 0 && sm[0] < 0.01f) g_flag = 1;
}

// ---------------- driver ----------------
extern "C" void kernel_launch(void* const* d_in, const int* in_sizes, int n_in,
                              void* d_out, int out_size)
{
    const float* H = (const float*)d_in[0];
    float* out = (float*)d_out;

    float *X0, *X1, *S, *P, *v, *y, *part, *scal;
    __half *hA, *lA, *hAT, *lAT, *hS, *lS, *hP, *lP;
    cudaGetSymbolAddress((void**)&X0, g_X0);   cudaGetSymbolAddress((void**)&X1, g_X1);
    cudaGetSymbolAddress((void**)&S, g_S);     cudaGetSymbolAddress((void**)&P, g_P);
    cudaGetSymbolAddress((void**)&hA, g_hA);   cudaGetSymbolAddress((void**)&lA, g_lA);
    cudaGetSymbolAddress((void**)&hAT, g_hAT); cudaGetSymbolAddress((void**)&lAT, g_lAT);
    cudaGetSymbolAddress((void**)&hS, g_hS);   cudaGetSymbolAddress((void**)&lS, g_lS);
    cudaGetSymbolAddress((void**)&hP, g_hP);   cudaGetSymbolAddress((void**)&lP, g_lP);
    cudaGetSymbolAddress((void**)&v, g_v);     cudaGetSymbolAddress((void**)&y, g_y);
    cudaGetSymbolAddress((void**)&part, g_part); cudaGetSymbolAddress((void**)&scal, g_scal);

    k_reset<<<1, 1>>>();

    // --- spectral norm estimate: 10 power iterations, Rayleigh lower bound ---
    k_initv<<<(MATN + 255) / 256, 256>>>(v);
    for (int t = 0; t < 10; ++t) {
        k_sumsq<<<256, 256>>>(v, MATN, part);
        k_finish<<<1, 256>>>(part, scal + 2);
        k_normalize<<<(MATN + 255) / 256, 256>>>(v, scal + 2);
        k_mvn<<<MATN, 128>>>(H, v, y);
        k_mvt<<<MATN / 32, 256>>>(H, y, v);
    }
    k_sumsq<<<256, 256>>>(v, MATN, part);
    k_finish<<<1, 256>>>(part, scal + 2);
    k_normalize<<<(MATN + 255) / 256, 256>>>(v, scal + 2);
    k_mvn<<<MATN, 128>>>(H, v, y);
    k_sumsq<<<256, 256>>>(y, MATN, part);
    k_finish<<<1, 256>>>(part, scal + 1);   // scal[1] = sigma_ray^2

    // --- schedule: 1 x L125, 7 x LA, 1 x COMP, 2 x NS  (11 steps) ---
    const int NSTEP = 11;
    const int NRAW  = 6;   // steps 0..5 use raw-fp16 S,P and 2-seg X'
    float ca[NSTEP], cb[NSTEP], cc[NSTEP];
    for (int i = 0; i < NSTEP; ++i) {
        if (i == 0)      { ca[i] = 3.140664f;  cb[i] = -5.165150f;  cc[i] = 2.346307f; }
        else if (i <= 7) { ca[i] = 3.9258326f; cb[i] = -10.0881832f; cc[i] = 7.1603506f; }
        else if (i == 8) { ca[i] = 2.8426f;    cb[i] = -4.4442f;    cc[i] = 2.6015f; }
        else             { ca[i] = 1.875f;     cb[i] = -1.25f;      cc[i] = 0.375f; }
    }

    dim3 grd(MATN / 128, MATN / 128);   // (32, 32)
    dim3 g32(MATN / 32, MATN / 32);
    dim3 b32(32, 8);
    float* Xc = X0;
    float* Xn = X1;

    for (int st = 0; st < NSTEP; ++st) {
        float* dst = (st == NSTEP - 1) ? out : Xn;
        const float a = ca[st], b = cb[st], c = cc[st];
        const bool raw = (st < NRAW);

        k_latch<<<1, 1>>>();
        k_copy_if<<<1024, 256>>>((st == 0) ? X0 : Xc, dst);

        k_splitT<<<g32, b32>>>((st == 0) ? H : Xc, hA, lA, hAT, lAT, (st == 0) ? 1 : 0);

        // S = X^T X  (upper tiles)
        if (raw) {
            mma_gemm<0, 1><<<grd, 256>>>(hAT, hAT, hAT, hAT, hAT, hAT, 1, S, nullptr, 0, 0, 0);
            k_mirsplit<<<g32, b32>>>(S, hS, lS, 0);
        } else {
            mma_gemm<0, 1><<<grd, 256>>>(hAT, hAT, hAT, lAT, lAT, hAT, 3, S, nullptr, 0, 0, 0);
            k_mirsplit<<<g32, b32>>>(S, hS, lS, 1);
        }

        k_resid<<<256, 256>>>(S, part);
        k_detect<<<1, 256>>>(part);

        // P = a I + b S + c S^2  (upper tiles; b-term uses exact fp32 S)
        if (raw) {
            mma_gemm<1, 1><<<grd, 256>>>(hS, hS, hS, hS, hS, hS, 1, P, S, a, b, c);
            k_mirsplit<<<g32, b32>>>(P, hP, lP, 0);
            // X' = (Xh + Xl) * Ph   (2 segs)
            mma_gemm<0, 0><<<grd, 256>>>(hA, hP, lA, hP, hA, hP, 2, dst, nullptr, 0, 0, 0);
        } else {
            mma_gemm<1, 1><<<grd, 256>>>(hS, hS, hS, lS, lS, hS, 3, P, S, a, b, c);
            k_mirsplit<<<g32, b32>>>(P, hP, lP, 1);
            // X' = Xh*Ph + Xh*Pl + Xl*Ph
            mma_gemm<0, 0><<<grd, 256>>>(hA, hP, hA, lP, lA, hP, 3, dst, nullptr, 0, 0, 0);
        }

        float* t = Xc; Xc = Xn; Xn = t;
        if (st == 0) Xc = X1;
    }
}

// round 10
// speedup vs baseline: 2.4724x; 1.2134x over previous
#include <cuda_runtime.h>
#include <cuda_fp16.h>
#include <cstdint>
#include <math.h>

#define MATN 4096
#define NSQL ((size_t)MATN * (size_t)MATN)

// ---------------- static device scratch ----------------
__device__ float g_X0[MATN * MATN];
__device__ float g_X1[MATN * MATN];
__device__ float g_S [MATN * MATN];
__device__ float g_P [MATN * MATN];
__device__ __half g_hA [MATN * MATN];
__device__ __half g_lA [MATN * MATN];
__device__ __half g_hAT[MATN * MATN];
__device__ __half g_lAT[MATN * MATN];
__device__ __half g_hS [MATN * MATN];
__device__ __half g_lS [MATN * MATN];
__device__ __half g_hP [MATN * MATN];
__device__ __half g_lP [MATN * MATN];
__device__ float g_v[MATN];
__device__ float g_y[MATN];
__device__ float g_part[256];
__device__ float g_scal[4];    // [1]=sigma_ray^2  [2]=tmp norm
__device__ int   g_flag;
__device__ int   g_flagL;

// ---------------- helpers ----------------
__device__ __forceinline__ uint32_t smem_u32(const void* p) {
    uint32_t a;
    asm("{ .reg .u64 t; cvta.to.shared.u64 t, %1; cvt.u32.u64 %0, t; }" : "=r"(a) : "l"(p));
    return a;
}
__device__ __forceinline__ void cp16(uint32_t dst, const void* src) {
    asm volatile("cp.async.cg.shared.global [%0], [%1], 16;" :: "r"(dst), "l"(src));
}
#define CP_COMMIT() asm volatile("cp.async.commit_group;" ::: "memory")
#define CP_WAIT(N)  asm volatile("cp.async.wait_group %0;" :: "n"(N) : "memory")

#define LDSM_X4(r, a)                                                           \
    asm volatile("ldmatrix.sync.aligned.m8n8.x4.shared.b16 {%0,%1,%2,%3}, [%4];" \
        : "=r"((r)[0]), "=r"((r)[1]), "=r"((r)[2]), "=r"((r)[3]) : "r"(a))

__device__ __forceinline__ void mma_f16(float* d, const uint32_t* a,
                                        uint32_t b0, uint32_t b1) {
    asm volatile(
        "mma.sync.aligned.m16n8k16.row.col.f32.f16.f16.f32 "
        "{%0,%1,%2,%3}, {%4,%5,%6,%7}, {%8,%9}, {%0,%1,%2,%3};"
        : "+f"(d[0]), "+f"(d[1]), "+f"(d[2]), "+f"(d[3])
        : "r"(a[0]), "r"(a[1]), "r"(a[2]), "r"(a[3]), "r"(b0), "r"(b1));
}

// ---------------- fp16 tensor-core GEMM (mma.sync) ----------------
// C = sum_s A_s * B_s^T ; POLY=1: C = c2*D + c1*E + c0*I.
// TRI=1: compute only tiles with col-tile >= row-tile (upper triangle).
#define BROW 80
#define ABYTES (128 * BROW)
#define BUFBYTES (2 * ABYTES)

template<int POLY, int TRI>
__global__ void __launch_bounds__(256, 2)
mma_gemm(const __half* __restrict__ A0, const __half* __restrict__ B0,
         const __half* __restrict__ A1, const __half* __restrict__ B1,
         const __half* __restrict__ A2, const __half* __restrict__ B2,
         int nseg, float* __restrict__ C, const float* __restrict__ E,
         float c0, float c1, float c2)
{
    if (g_flagL) return;
    if (TRI && (int)blockIdx.x < (int)blockIdx.y) return;
    __shared__ __align__(16) char smem[2 * BUFBYTES];
    const uint32_t sbase = smem_u32(smem);

    const int tid  = threadIdx.x;
    const int wid  = tid >> 5, lane = tid & 31;
    const int wr   = wid & 3;
    const int wc   = wid >> 2;
    const int row0 = blockIdx.y * 128;
    const int col0 = blockIdx.x * 128;

    const __half* Aseg[3] = {A0, A1, A2};
    const __half* Bseg[3] = {B0, B1, B2};

    float acc[2][8][4];
    #pragma unroll
    for (int i = 0; i < 2; ++i)
        #pragma unroll
        for (int j = 0; j < 8; ++j)
            #pragma unroll
            for (int k = 0; k < 4; ++k) acc[i][j][k] = 0.f;

    auto load_chunk = [&](int ch, int buf) {
        const int seg = ch >> 7, kc = ch & 127;
        const __half* Ap = Aseg[seg] + (size_t)row0 * MATN + kc * 32;
        const __half* Bp = Bseg[seg] + (size_t)col0 * MATN + kc * 32;
        const uint32_t sa = sbase + buf * BUFBYTES;
        const uint32_t sb = sa + ABYTES;
        #pragma unroll
        for (int p = 0; p < 2; ++p) {
            int q = tid + p * 256;
            int r = q >> 2, s = q & 3;
            cp16(sa + r * BROW + s * 16, Ap + (size_t)r * MATN + s * 8);
            cp16(sb + r * BROW + s * 16, Bp + (size_t)r * MATN + s * 8);
        }
        CP_COMMIT();
    };

    const int total = nseg * 128;
    load_chunk(0, 0);

    for (int ch = 0; ch < total; ++ch) {
        const int buf = ch & 1;
        if (ch + 1 < total) { load_chunk(ch + 1, buf ^ 1); CP_WAIT(1); }
        else                { CP_WAIT(0); }
        __syncthreads();

        const uint32_t sa = sbase + buf * BUFBYTES;
        const uint32_t sb = sa + ABYTES;
        #pragma unroll
        for (int kk = 0; kk < 2; ++kk) {
            uint32_t af[2][4], bf[4][4];
            #pragma unroll
            for (int mt = 0; mt < 2; ++mt) {
                uint32_t addr = sa + (uint32_t)(wr * 32 + mt * 16 + (lane & 15)) * BROW
                              + kk * 32 + (lane >> 4) * 16;
                LDSM_X4(af[mt], addr);
            }
            #pragma unroll
            for (int bp = 0; bp < 4; ++bp) {
                int grp = lane >> 3, wi = lane & 7;
                uint32_t addr = sb + (uint32_t)(wc * 64 + bp * 16 + wi + (grp >> 1) * 8) * BROW
                              + kk * 32 + (grp & 1) * 16;
                LDSM_X4(bf[bp], addr);
            }
            #pragma unroll
            for (int mt = 0; mt < 2; ++mt)
                #pragma unroll
                for (int nt = 0; nt < 8; ++nt)
                    mma_f16(acc[mt][nt], af[mt], bf[nt >> 1][(nt & 1) * 2],
                            bf[nt >> 1][(nt & 1) * 2 + 1]);
        }
        __syncthreads();
    }

    #pragma unroll
    for (int mt = 0; mt < 2; ++mt) {
        #pragma unroll
        for (int half = 0; half < 2; ++half) {
            const int rg = row0 + wr * 32 + mt * 16 + (lane >> 2) + half * 8;
            const size_t rowbase = (size_t)rg * MATN;
            #pragma unroll
            for (int nt = 0; nt < 8; ++nt) {
                const int cc = col0 + wc * 64 + nt * 8 + (lane & 3) * 2;
                float v0 = acc[mt][nt][half * 2 + 0];
                float v1 = acc[mt][nt][half * 2 + 1];
                if (POLY) {
                    float2 e = *reinterpret_cast<const float2*>(E + rowbase + cc);
                    v0 = c2 * v0 + c1 * e.x + ((rg == cc)     ? c0 : 0.f);
                    v1 = c2 * v1 + c1 * e.y + ((rg == cc + 1) ? c0 : 0.f);
                }
                float2 o = make_float2(v0, v1);
                *reinterpret_cast<float2*>(C + rowbase + cc) = o;
            }
        }
    }
}

// ---------------- small kernels ----------------
__global__ void k_reset() { g_flag = 0; g_flagL = 0; }
__global__ void k_latch() { g_flagL = g_flag; }

__global__ void k_copy_if(const float* __restrict__ src, float* __restrict__ dst) {
    if (!g_flagL) return;
    for (size_t i = (size_t)blockIdx.x * blockDim.x + threadIdx.x; i < NSQL / 4;
         i += (size_t)gridDim.x * blockDim.x)
        reinterpret_cast<float4*>(dst)[i] = reinterpret_cast<const float4*>(src)[i];
}

__global__ void k_sumsq(const float* __restrict__ x, int n, float* __restrict__ part) {
    __shared__ float sm[256];
    float acc = 0.f;
    for (int i = blockIdx.x * blockDim.x + threadIdx.x; i < n; i += gridDim.x * blockDim.x) {
        float v = x[i]; acc = fmaf(v, v, acc);
    }
    sm[threadIdx.x] = acc; __syncthreads();
    for (int s = 128; s > 0; s >>= 1) {
        if (threadIdx.x < s) sm[threadIdx.x] += sm[threadIdx.x + s];
        __syncthreads();
    }
    if (threadIdx.x == 0) part[blockIdx.x] = sm[0];
}
__global__ void k_finish(const float* __restrict__ part, float* __restrict__ dst) {
    __shared__ float sm[256];
    sm[threadIdx.x] = part[threadIdx.x]; __syncthreads();
    for (int s = 128; s > 0; s >>= 1) {
        if (threadIdx.x < s) sm[threadIdx.x] += sm[threadIdx.x + s];
        __syncthreads();
    }
    if (threadIdx.x == 0) *dst = sm[0];
}

__global__ void k_initv(float* v) {
    int j = blockIdx.x * blockDim.x + threadIdx.x;
    if (j < MATN) {
        unsigned h = (unsigned)j * 2654435761u;
        h ^= h >> 13; h *= 0x5bd1e995u; h ^= h >> 15;
        v[j] = ((float)(h & 0xFFFFu) / 65536.0f) - 0.5f + 0.001f;
    }
}
__global__ void k_normalize(float* v, const float* n2) {
    int j = blockIdx.x * blockDim.x + threadIdx.x;
    float s = rsqrtf(*n2 + 1e-30f);
    if (j < MATN) v[j] *= s;
}
__global__ void k_mvn(const float* __restrict__ H, const float* __restrict__ v,
                      float* __restrict__ y) {
    __shared__ float sm[128];
    int r = blockIdx.x;
    const float* row = H + (size_t)r * MATN;
    float acc = 0.f;
    for (int j = threadIdx.x; j < MATN; j += 128) acc = fmaf(row[j], v[j], acc);
    sm[threadIdx.x] = acc; __syncthreads();
    for (int s = 64; s > 0; s >>= 1) {
        if (threadIdx.x < s) sm[threadIdx.x] += sm[threadIdx.x + s];
        __syncthreads();
    }
    if (threadIdx.x == 0) y[r] = sm[0];
}
__global__ void k_mvt(const float* __restrict__ H, const float* __restrict__ y,
                      float* __restrict__ z) {
    __shared__ float sm[256];
    int tj = threadIdx.x & 31, gi = threadIdx.x >> 5;
    int j = blockIdx.x * 32 + tj;
    float acc = 0.f;
    for (int i = gi * 512; i < gi * 512 + 512; ++i)
        acc = fmaf(H[(size_t)i * MATN + j], y[i], acc);
    sm[threadIdx.x] = acc; __syncthreads();
    if (threadIdx.x < 32) {
        float t = 0.f;
        #pragma unroll
        for (int g = 0; g < 8; ++g) t += sm[threadIdx.x + 32 * g];
        z[j] = t;
    }
}

// split X -> (hi, lo) and transposed copies; optional prescale from g_scal[1]
__global__ void k_splitT(const float* __restrict__ X,
                         __half* __restrict__ hi, __half* __restrict__ lo,
                         __half* __restrict__ hiT, __half* __restrict__ loT,
                         int prescale) {
    if (g_flagL) return;
    __shared__ float t[32][33];
    float s = prescale ? (rsqrtf(g_scal[1] + 1e-30f) / 1.10f) : 1.0f;
    int x0 = blockIdx.x * 32, y0 = blockIdx.y * 32;
    #pragma unroll
    for (int j = 0; j < 32; j += 8) {
        int r = y0 + threadIdx.y + j, c = x0 + threadIdx.x;
        float v = X[(size_t)r * MATN + c] * s;
        t[threadIdx.y + j][threadIdx.x] = v;
        __half h = __float2half(v);
        hi[(size_t)r * MATN + c] = h;
        lo[(size_t)r * MATN + c] = __float2half(v - __half2float(h));
    }
    __syncthreads();
    #pragma unroll
    for (int j = 0; j < 32; j += 8) {
        int r = x0 + threadIdx.y + j, c = y0 + threadIdx.x;
        float v = t[threadIdx.x][threadIdx.y + j];
        __half h = __float2half(v);
        hiT[(size_t)r * MATN + c] = h;
        loT[(size_t)r * MATN + c] = __float2half(v - __half2float(h));
    }
}

// read upper tile of S (bj>=bi), split (hi always, lo if wlo) at (i,j) and mirror (j,i)
__global__ void k_mirsplit(float* __restrict__ S,
                           __half* __restrict__ hi, __half* __restrict__ lo, int wlo) {
    if (g_flagL) return;
    __shared__ float ta[32][33];
    int bi = blockIdx.y, bj = blockIdx.x;
    if (bj < bi) return;
    int i0 = bi * 32, j0 = bj * 32;
    #pragma unroll
    for (int j = 0; j < 32; j += 8) {
        size_t idx1 = (size_t)(i0 + threadIdx.y + j) * MATN + j0 + threadIdx.x;
        float v = S[idx1];
        ta[threadIdx.y + j][threadIdx.x] = v;
        __half h = __float2half(v);
        hi[idx1] = h;
        if (wlo) lo[idx1] = __float2half(v - __half2float(h));
    }
    if (bi == bj) return;
    __syncthreads();
    #pragma unroll
    for (int j = 0; j < 32; j += 8) {
        size_t idx2 = (size_t)(j0 + threadIdx.y + j) * MATN + i0 + threadIdx.x;
        float v = ta[threadIdx.x][threadIdx.y + j];
        S[idx2] = v;
        __half h = __float2half(v);
        hi[idx2] = h;
        if (wlo) lo[idx2] = __float2half(v - __half2float(h));
    }
}

__global__ void k_resid(const float* __restrict__ S, float* __restrict__ part) {
    __shared__ float sm[256];
    float acc = 0.f;
    if (!g_flagL) {
        for (size_t i = (size_t)blockIdx.x * blockDim.x + threadIdx.x; i < NSQL;
             i += (size_t)gridDim.x * blockDim.x) {
            float d = S[i] - ((i / MATN == i % MATN) ? 1.f : 0.f);
            acc = fmaf(d, d, acc);
        }
    }
    sm[threadIdx.x] = acc; __syncthreads();
    for (int s = 128; s > 0; s >>= 1) {
        if (threadIdx.x < s) sm[threadIdx.x] += sm[threadIdx.x + s];
        __syncthreads();
    }
    if (threadIdx.x == 0) part[blockIdx.x] = sm[0];
}
__global__ void k_detect(const float* __restrict__ part) {
    if (g_flagL) return;
    __shared__ float sm[256];
    sm[threadIdx.x] = part[threadIdx.x]; __syncthreads();
    for (int s = 128; s > 0; s >>= 1) {
        if (threadIdx.x < s) sm[threadIdx.x] += sm[threadIdx.x + s];
        __syncthreads();
    }
    if (threadIdx.x == 0 && sm[0] < 0.01f) g_flag = 1;
}

// ---------------- driver ----------------
extern "C" void kernel_launch(void* const* d_in, const int* in_sizes, int n_in,
                              void* d_out, int out_size)
{
    const float* H = (const float*)d_in[0];
    float* out = (float*)d_out;

    float *X0, *X1, *S, *P, *v, *y, *part, *scal;
    __half *hA, *lA, *hAT, *lAT, *hS, *lS, *hP, *lP;
    cudaGetSymbolAddress((void**)&X0, g_X0);   cudaGetSymbolAddress((void**)&X1, g_X1);
    cudaGetSymbolAddress((void**)&S, g_S);     cudaGetSymbolAddress((void**)&P, g_P);
    cudaGetSymbolAddress((void**)&hA, g_hA);   cudaGetSymbolAddress((void**)&lA, g_lA);
    cudaGetSymbolAddress((void**)&hAT, g_hAT); cudaGetSymbolAddress((void**)&lAT, g_lAT);
    cudaGetSymbolAddress((void**)&hS, g_hS);   cudaGetSymbolAddress((void**)&lS, g_lS);
    cudaGetSymbolAddress((void**)&hP, g_hP);   cudaGetSymbolAddress((void**)&lP, g_lP);
    cudaGetSymbolAddress((void**)&v, g_v);     cudaGetSymbolAddress((void**)&y, g_y);
    cudaGetSymbolAddress((void**)&part, g_part); cudaGetSymbolAddress((void**)&scal, g_scal);

    k_reset<<<1, 1>>>();

    // --- spectral norm estimate: 10 power iterations, Rayleigh lower bound ---
    k_initv<<<(MATN + 255) / 256, 256>>>(v);
    for (int t = 0; t < 10; ++t) {
        k_sumsq<<<256, 256>>>(v, MATN, part);
        k_finish<<<1, 256>>>(part, scal + 2);
        k_normalize<<<(MATN + 255) / 256, 256>>>(v, scal + 2);
        k_mvn<<<MATN, 128>>>(H, v, y);
        k_mvt<<<MATN / 32, 256>>>(H, y, v);
    }
    k_sumsq<<<256, 256>>>(v, MATN, part);
    k_finish<<<1, 256>>>(part, scal + 2);
    k_normalize<<<(MATN + 255) / 256, 256>>>(v, scal + 2);
    k_mvn<<<MATN, 128>>>(H, v, y);
    k_sumsq<<<256, 256>>>(y, MATN, part);
    k_finish<<<1, 256>>>(part, scal + 1);   // scal[1] = sigma_ray^2

    // --- schedule: 1 x L125, 7 x LA, 1 x COMP, 2 x NS  (11 steps) ---
    // steps 0..5 : raw     (raw S, raw P, X' = fullX * Ph, 2 segs)
    // steps 6..9 : semiraw (raw S, raw P, X' fully split, 3 segs)
    // step  10   : full    (split S, split P, X' fully split)
    const int NSTEP = 11;
    float ca[NSTEP], cb[NSTEP], cc[NSTEP];
    for (int i = 0; i < NSTEP; ++i) {
        if (i == 0)      { ca[i] = 3.140664f;  cb[i] = -5.165150f;  cc[i] = 2.346307f; }
        else if (i <= 7) { ca[i] = 3.9258326f; cb[i] = -10.0881832f; cc[i] = 7.1603506f; }
        else if (i == 8) { ca[i] = 2.8426f;    cb[i] = -4.4442f;    cc[i] = 2.6015f; }
        else             { ca[i] = 1.875f;     cb[i] = -1.25f;      cc[i] = 0.375f; }
    }

    dim3 grd(MATN / 128, MATN / 128);   // (32, 32)
    dim3 g32(MATN / 32, MATN / 32);
    dim3 b32(32, 8);
    float* Xc = X0;
    float* Xn = X1;

    for (int st = 0; st < NSTEP; ++st) {
        float* dst = (st == NSTEP - 1) ? out : Xn;
        const float a = ca[st], b = cb[st], c = cc[st];
        const bool fullS = (st == NSTEP - 1);    // last step: exact split S and P
        const bool splitX = (st >= 6);           // semiraw/full: 3-seg X'

        if (st >= 7) {
            k_latch<<<1, 1>>>();
            k_copy_if<<<1024, 256>>>(Xc, dst);
        }

        k_splitT<<<g32, b32>>>((st == 0) ? H : Xc, hA, lA, hAT, lAT, (st == 0) ? 1 : 0);

        // S = X^T X  (upper tiles)
        if (fullS)
            mma_gemm<0, 1><<<grd, 256>>>(hAT, hAT, hAT, lAT, lAT, hAT, 3, S, nullptr, 0, 0, 0);
        else
            mma_gemm<0, 1><<<grd, 256>>>(hAT, hAT, hAT, hAT, hAT, hAT, 1, S, nullptr, 0, 0, 0);
        k_mirsplit<<<g32, b32>>>(S, hS, lS, fullS ? 1 : 0);

        if (st >= 6) {
            k_resid<<<256, 256>>>(S, part);
            k_detect<<<1, 256>>>(part);
        }

        // P = a I + b S + c S^2  (upper tiles; b-term reads exact fp32 S)
        if (fullS)
            mma_gemm<1, 1><<<grd, 256>>>(hS, hS, hS, lS, lS, hS, 3, P, S, a, b, c);
        else
            mma_gemm<1, 1><<<grd, 256>>>(hS, hS, hS, hS, hS, hS, 1, P, S, a, b, c);
        k_mirsplit<<<g32, b32>>>(P, hP, lP, splitX ? 1 : 0);

        // X'
        if (splitX)
            mma_gemm<0, 0><<<grd, 256>>>(hA, hP, hA, lP, lA, hP, 3, dst, nullptr, 0, 0, 0);
        else
            mma_gemm<0, 0><<<grd, 256>>>(hA, hP, lA, hP, hA, hP, 2, dst, nullptr, 0, 0, 0);

        float* t = Xc; Xc = Xn; Xn = t;
        if (st == 0) Xc = X1;
    }
}

// round 12
// speedup vs baseline: 2.5105x; 1.0154x over previous
#include <cuda_runtime.h>
#include <cuda_fp16.h>
#include <cstdint>
#include <math.h>

#define MATN 4096
#define NSQL ((size_t)MATN * (size_t)MATN)

// ---------------- static device scratch ----------------
__device__ float g_X0[MATN * MATN];
__device__ float g_X1[MATN * MATN];
__device__ float g_S [MATN * MATN];
__device__ float g_P [MATN * MATN];
__device__ __half g_hA [MATN * MATN];
__device__ __half g_lA [MATN * MATN];
__device__ __half g_hAT[MATN * MATN];
__device__ __half g_lAT[MATN * MATN];
__device__ __half g_hS [MATN * MATN];
__device__ __half g_lS [MATN * MATN];
__device__ __half g_hP [MATN * MATN];
__device__ __half g_lP [MATN * MATN];
__device__ float g_v[MATN];
__device__ float g_y[MATN];
__device__ float g_part[256];
__device__ float g_scal[4];    // [1]=sigma_ray^2  [2]=tmp norm

// ---------------- helpers ----------------
__device__ __forceinline__ uint32_t smem_u32(const void* p) {
    uint32_t a;
    asm("{ .reg .u64 t; cvta.to.shared.u64 t, %1; cvt.u32.u64 %0, t; }" : "=r"(a) : "l"(p));
    return a;
}
__device__ __forceinline__ void cp16(uint32_t dst, const void* src) {
    asm volatile("cp.async.cg.shared.global [%0], [%1], 16;" :: "r"(dst), "l"(src));
}
#define CP_COMMIT() asm volatile("cp.async.commit_group;" ::: "memory")
#define CP_WAIT(N)  asm volatile("cp.async.wait_group %0;" :: "n"(N) : "memory")

#define LDSM_X4(r, a)                                                           \
    asm volatile("ldmatrix.sync.aligned.m8n8.x4.shared.b16 {%0,%1,%2,%3}, [%4];" \
        : "=r"((r)[0]), "=r"((r)[1]), "=r"((r)[2]), "=r"((r)[3]) : "r"(a))

__device__ __forceinline__ void mma_f16(float* d, const uint32_t* a,
                                        uint32_t b0, uint32_t b1) {
    asm volatile(
        "mma.sync.aligned.m16n8k16.row.col.f32.f16.f16.f32 "
        "{%0,%1,%2,%3}, {%4,%5,%6,%7}, {%8,%9}, {%0,%1,%2,%3};"
        : "+f"(d[0]), "+f"(d[1]), "+f"(d[2]), "+f"(d[3])
        : "r"(a[0]), "r"(a[1]), "r"(a[2]), "r"(a[3]), "r"(b0), "r"(b1));
}

// ---------------- fp16 tensor-core GEMM (mma.sync) ----------------
// C = sum_s A_s * B_s^T ; POLY=1: C = c2*D + c1*E + c0*I.
// TRI=1: compute only tiles with col-tile >= row-tile (upper triangle).
// Optional fused split: if Hi != null, also write half(C) (and residual to Lo).
#define BROW 80
#define ABYTES (128 * BROW)
#define BUFBYTES (2 * ABYTES)

template<int POLY, int TRI>
__global__ void __launch_bounds__(256, 2)
mma_gemm(const __half* __restrict__ A0, const __half* __restrict__ B0,
         const __half* __restrict__ A1, const __half* __restrict__ B1,
         const __half* __restrict__ A2, const __half* __restrict__ B2,
         int nseg, float* __restrict__ C, const float* __restrict__ E,
         float c0, float c1, float c2,
         __half* __restrict__ Hi, __half* __restrict__ Lo)
{
    if (TRI && (int)blockIdx.x < (int)blockIdx.y) return;
    __shared__ __align__(16) char smem[2 * BUFBYTES];
    const uint32_t sbase = smem_u32(smem);

    const int tid  = threadIdx.x;
    const int wid  = tid >> 5, lane = tid & 31;
    const int wr   = wid & 3;
    const int wc   = wid >> 2;
    const int row0 = blockIdx.y * 128;
    const int col0 = blockIdx.x * 128;

    const __half* Aseg[3] = {A0, A1, A2};
    const __half* Bseg[3] = {B0, B1, B2};

    float acc[2][8][4];
    #pragma unroll
    for (int i = 0; i < 2; ++i)
        #pragma unroll
        for (int j = 0; j < 8; ++j)
            #pragma unroll
            for (int k = 0; k < 4; ++k) acc[i][j][k] = 0.f;

    auto load_chunk = [&](int ch, int buf) {
        const int seg = ch >> 7, kc = ch & 127;
        const __half* Ap = Aseg[seg] + (size_t)row0 * MATN + kc * 32;
        const __half* Bp = Bseg[seg] + (size_t)col0 * MATN + kc * 32;
        const uint32_t sa = sbase + buf * BUFBYTES;
        const uint32_t sb = sa + ABYTES;
        #pragma unroll
        for (int p = 0; p < 2; ++p) {
            int q = tid + p * 256;
            int r = q >> 2, s = q & 3;
            cp16(sa + r * BROW + s * 16, Ap + (size_t)r * MATN + s * 8);
            cp16(sb + r * BROW + s * 16, Bp + (size_t)r * MATN + s * 8);
        }
        CP_COMMIT();
    };

    const int total = nseg * 128;
    load_chunk(0, 0);

    for (int ch = 0; ch < total; ++ch) {
        const int buf = ch & 1;
        if (ch + 1 < total) { load_chunk(ch + 1, buf ^ 1); CP_WAIT(1); }
        else                { CP_WAIT(0); }
        __syncthreads();

        const uint32_t sa = sbase + buf * BUFBYTES;
        const uint32_t sb = sa + ABYTES;
        #pragma unroll
        for (int kk = 0; kk < 2; ++kk) {
            uint32_t af[2][4], bf[4][4];
            #pragma unroll
            for (int mt = 0; mt < 2; ++mt) {
                uint32_t addr = sa + (uint32_t)(wr * 32 + mt * 16 + (lane & 15)) * BROW
                              + kk * 32 + (lane >> 4) * 16;
                LDSM_X4(af[mt], addr);
            }
            #pragma unroll
            for (int bp = 0; bp < 4; ++bp) {
                int grp = lane >> 3, wi = lane & 7;
                uint32_t addr = sb + (uint32_t)(wc * 64 + bp * 16 + wi + (grp >> 1) * 8) * BROW
                              + kk * 32 + (grp & 1) * 16;
                LDSM_X4(bf[bp], addr);
            }
            #pragma unroll
            for (int mt = 0; mt < 2; ++mt)
                #pragma unroll
                for (int nt = 0; nt < 8; ++nt)
                    mma_f16(acc[mt][nt], af[mt], bf[nt >> 1][(nt & 1) * 2],
                            bf[nt >> 1][(nt & 1) * 2 + 1]);
        }
        __syncthreads();
    }

    #pragma unroll
    for (int mt = 0; mt < 2; ++mt) {
        #pragma unroll
        for (int half = 0; half < 2; ++half) {
            const int rg = row0 + wr * 32 + mt * 16 + (lane >> 2) + half * 8;
            const size_t rowbase = (size_t)rg * MATN;
            #pragma unroll
            for (int nt = 0; nt < 8; ++nt) {
                const int cc = col0 + wc * 64 + nt * 8 + (lane & 3) * 2;
                float v0 = acc[mt][nt][half * 2 + 0];
                float v1 = acc[mt][nt][half * 2 + 1];
                if (POLY) {
                    float2 e = *reinterpret_cast<const float2*>(E + rowbase + cc);
                    v0 = c2 * v0 + c1 * e.x + ((rg == cc)     ? c0 : 0.f);
                    v1 = c2 * v1 + c1 * e.y + ((rg == cc + 1) ? c0 : 0.f);
                }
                float2 o = make_float2(v0, v1);
                *reinterpret_cast<float2*>(C + rowbase + cc) = o;
                if (Hi) {
                    __half2 hh = __floats2half2_rn(v0, v1);
                    *reinterpret_cast<__half2*>(Hi + rowbase + cc) = hh;
                    if (Lo) {
                        float l0 = v0 - __half2float(__low2half(hh));
                        float l1 = v1 - __half2float(__high2half(hh));
                        *reinterpret_cast<__half2*>(Lo + rowbase + cc) =
                            __floats2half2_rn(l0, l1);
                    }
                }
            }
        }
    }
}

// ---------------- small kernels ----------------
__global__ void k_sumsq(const float* __restrict__ x, int n, float* __restrict__ part) {
    __shared__ float sm[256];
    float acc = 0.f;
    for (int i = blockIdx.x * blockDim.x + threadIdx.x; i < n; i += gridDim.x * blockDim.x) {
        float v = x[i]; acc = fmaf(v, v, acc);
    }
    sm[threadIdx.x] = acc; __syncthreads();
    for (int s = 128; s > 0; s >>= 1) {
        if (threadIdx.x < s) sm[threadIdx.x] += sm[threadIdx.x + s];
        __syncthreads();
    }
    if (threadIdx.x == 0) part[blockIdx.x] = sm[0];
}
__global__ void k_finish(const float* __restrict__ part, float* __restrict__ dst) {
    __shared__ float sm[256];
    sm[threadIdx.x] = part[threadIdx.x]; __syncthreads();
    for (int s = 128; s > 0; s >>= 1) {
        if (threadIdx.x < s) sm[threadIdx.x] += sm[threadIdx.x + s];
        __syncthreads();
    }
    if (threadIdx.x == 0) *dst = sm[0];
}

__global__ void k_initv(float* v) {
    int j = blockIdx.x * blockDim.x + threadIdx.x;
    if (j < MATN) {
        unsigned h = (unsigned)j * 2654435761u;
        h ^= h >> 13; h *= 0x5bd1e995u; h ^= h >> 15;
        v[j] = ((float)(h & 0xFFFFu) / 65536.0f) - 0.5f + 0.001f;
    }
}
__global__ void k_normalize(float* v, const float* n2) {
    int j = blockIdx.x * blockDim.x + threadIdx.x;
    float s = rsqrtf(*n2 + 1e-30f);
    if (j < MATN) v[j] *= s;
}
__global__ void k_mvn(const float* __restrict__ H, const float* __restrict__ v,
                      float* __restrict__ y) {
    __shared__ float sm[128];
    int r = blockIdx.x;
    const float* row = H + (size_t)r * MATN;
    float acc = 0.f;
    for (int j = threadIdx.x; j < MATN; j += 128) acc = fmaf(row[j], v[j], acc);
    sm[threadIdx.x] = acc; __syncthreads();
    for (int s = 64; s > 0; s >>= 1) {
        if (threadIdx.x < s) sm[threadIdx.x] += sm[threadIdx.x + s];
        __syncthreads();
    }
    if (threadIdx.x == 0) y[r] = sm[0];
}
__global__ void k_mvt(const float* __restrict__ H, const float* __restrict__ y,
                      float* __restrict__ z) {
    __shared__ float sm[256];
    int tj = threadIdx.x & 31, gi = threadIdx.x >> 5;
    int j = blockIdx.x * 32 + tj;
    float acc = 0.f;
    for (int i = gi * 512; i < gi * 512 + 512; ++i)
        acc = fmaf(H[(size_t)i * MATN + j], y[i], acc);
    sm[threadIdx.x] = acc; __syncthreads();
    if (threadIdx.x < 32) {
        float t = 0.f;
        #pragma unroll
        for (int g = 0; g < 8; ++g) t += sm[threadIdx.x + 32 * g];
        z[j] = t;
    }
}

// split X -> (hi, lo) and transposed copies; optional prescale from g_scal[1]
__global__ void k_splitT(const float* __restrict__ X,
                         __half* __restrict__ hi, __half* __restrict__ lo,
                         __half* __restrict__ hiT, __half* __restrict__ loT,
                         int prescale) {
    __shared__ float t[32][33];
    float s = prescale ? (rsqrtf(g_scal[1] + 1e-30f) / 1.10f) : 1.0f;
    int x0 = blockIdx.x * 32, y0 = blockIdx.y * 32;
    #pragma unroll
    for (int j = 0; j < 32; j += 8) {
        int r = y0 + threadIdx.y + j, c = x0 + threadIdx.x;
        float v = X[(size_t)r * MATN + c] * s;
        t[threadIdx.y + j][threadIdx.x] = v;
        __half h = __float2half(v);
        hi[(size_t)r * MATN + c] = h;
        lo[(size_t)r * MATN + c] = __float2half(v - __half2float(h));
    }
    __syncthreads();
    #pragma unroll
    for (int j = 0; j < 32; j += 8) {
        int r = x0 + threadIdx.y + j, c = y0 + threadIdx.x;
        float v = t[threadIdx.x][threadIdx.y + j];
        __half h = __float2half(v);
        hiT[(size_t)r * MATN + c] = h;
        loT[(size_t)r * MATN + c] = __float2half(v - __half2float(h));
    }
}

// mirror upper->lower (strictly below diagonal): fp32 + hi (+ lo if wlo)
__global__ void k_mirror(float* __restrict__ M,
                         __half* __restrict__ hi, __half* __restrict__ lo, int wlo) {
    __shared__ float ta[32][33];
    int bi = blockIdx.y, bj = blockIdx.x;
    if (bj <= bi) return;
    int i0 = bi * 32, j0 = bj * 32;
    #pragma unroll
    for (int j = 0; j < 32; j += 8)
        ta[threadIdx.y + j][threadIdx.x] =
            M[(size_t)(i0 + threadIdx.y + j) * MATN + j0 + threadIdx.x];
    __syncthreads();
    #pragma unroll
    for (int j = 0; j < 32; j += 8) {
        size_t idx2 = (size_t)(j0 + threadIdx.y + j) * MATN + i0 + threadIdx.x;
        float v = ta[threadIdx.x][threadIdx.y + j];
        M[idx2] = v;
        __half h = __float2half(v);
        hi[idx2] = h;
        if (wlo) lo[idx2] = __float2half(v - __half2float(h));
    }
}

// ---------------- driver ----------------
extern "C" void kernel_launch(void* const* d_in, const int* in_sizes, int n_in,
                              void* d_out, int out_size)
{
    const float* H = (const float*)d_in[0];
    float* out = (float*)d_out;

    float *X0, *X1, *S, *P, *v, *y, *part, *scal;
    __half *hA, *lA, *hAT, *lAT, *hS, *lS, *hP, *lP;
    cudaGetSymbolAddress((void**)&X0, g_X0);   cudaGetSymbolAddress((void**)&X1, g_X1);
    cudaGetSymbolAddress((void**)&S, g_S);     cudaGetSymbolAddress((void**)&P, g_P);
    cudaGetSymbolAddress((void**)&hA, g_hA);   cudaGetSymbolAddress((void**)&lA, g_lA);
    cudaGetSymbolAddress((void**)&hAT, g_hAT); cudaGetSymbolAddress((void**)&lAT, g_lAT);
    cudaGetSymbolAddress((void**)&hS, g_hS);   cudaGetSymbolAddress((void**)&lS, g_lS);
    cudaGetSymbolAddress((void**)&hP, g_hP);   cudaGetSymbolAddress((void**)&lP, g_lP);
    cudaGetSymbolAddress((void**)&v, g_v);     cudaGetSymbolAddress((void**)&y, g_y);
    cudaGetSymbolAddress((void**)&part, g_part); cudaGetSymbolAddress((void**)&scal, g_scal);

    // --- spectral norm estimate: 10 power iterations, Rayleigh lower bound ---
    k_initv<<<(MATN + 255) / 256, 256>>>(v);
    for (int t = 0; t < 10; ++t) {
        k_sumsq<<<256, 256>>>(v, MATN, part);
        k_finish<<<1, 256>>>(part, scal + 2);
        k_normalize<<<(MATN + 255) / 256, 256>>>(v, scal + 2);
        k_mvn<<<MATN, 128>>>(H, v, y);
        k_mvt<<<MATN / 32, 256>>>(H, y, v);
    }
    k_sumsq<<<256, 256>>>(v, MATN, part);
    k_finish<<<1, 256>>>(part, scal + 2);
    k_normalize<<<(MATN + 255) / 256, 256>>>(v, scal + 2);
    k_mvn<<<MATN, 128>>>(H, v, y);
    k_sumsq<<<256, 256>>>(y, MATN, part);
    k_finish<<<1, 256>>>(part, scal + 1);   // scal[1] = sigma_ray^2

    // --- schedule: 1 x L125, 7 x LA, 1 x COMP, 2 x NS (11 steps), hardened 0.99 ---
    // steps 0..5 : raw     (raw S, raw P, X' = fullX * Ph, 2 segs)
    // steps 6..9 : semiraw (raw S, raw P, X' fully split, 3 segs)
    // step  10   : full    (split S, split P, X' fully split)
    const int NSTEP = 11;
    float ca[NSTEP], cb[NSTEP], cc[NSTEP];
    for (int i = 0; i < NSTEP; ++i) {
        if (i == 0)      { ca[i] = 3.115487f;  cb[i] = -5.123742f;   cc[i] = 2.327495f; }
        else if (i <= 7) { ca[i] = 3.894363f;  cb[i] = -10.007316f;  cc[i] = 7.102953f; }
        else if (i == 8) { ca[i] = 2.8426f;    cb[i] = -4.4442f;     cc[i] = 2.6015f; }
        else             { ca[i] = 1.875f;     cb[i] = -1.25f;       cc[i] = 0.375f; }
    }

    dim3 grd(MATN / 128, MATN / 128);   // (32, 32)
    dim3 g32(MATN / 32, MATN / 32);
    dim3 b32(32, 8);
    float* Xc = X0;
    float* Xn = X1;

    for (int st = 0; st < NSTEP; ++st) {
        float* dst = (st == NSTEP - 1) ? out : Xn;
        const float a = ca[st], b = cb[st], c = cc[st];
        const bool fullS = (st == NSTEP - 1);    // last step: exact split S and P
        const bool splitX = (st >= 6);           // semiraw/full: 3-seg X'

        k_splitT<<<g32, b32>>>((st == 0) ? H : Xc, hA, lA, hAT, lAT, (st == 0) ? 1 : 0);

        // S = X^T X  (upper tiles, fused split in epilogue)
        if (fullS)
            mma_gemm<0, 1><<<grd, 256>>>(hAT, hAT, hAT, lAT, lAT, hAT, 3, S, nullptr,
                                         0, 0, 0, hS, lS);
        else
            mma_gemm<0, 1><<<grd, 256>>>(hAT, hAT, hAT, hAT, hAT, hAT, 1, S, nullptr,
                                         0, 0, 0, hS, nullptr);
        k_mirror<<<g32, b32>>>(S, hS, lS, fullS ? 1 : 0);

        // P = a I + b S + c S^2  (upper tiles; b-term reads exact fp32 S)
        if (fullS)
            mma_gemm<1, 1><<<grd, 256>>>(hS, hS, hS, lS, lS, hS, 3, P, S, a, b, c,
                                         hP, lP);
        else
            mma_gemm<1, 1><<<grd, 256>>>(hS, hS, hS, hS, hS, hS, 1, P, S, a, b, c,
                                         hP, splitX ? lP : nullptr);
        k_mirror<<<g32, b32>>>(P, hP, lP, splitX ? 1 : 0);

        // X'
        if (splitX)
            mma_gemm<0, 0><<<grd, 256>>>(hA, hP, hA, lP, lA, hP, 3, dst, nullptr,
                                         0, 0, 0, nullptr, nullptr);
        else
            mma_gemm<0, 0><<<grd, 256>>>(hA, hP, lA, hP, hA, hP, 2, dst, nullptr,
                                         0, 0, 0, nullptr, nullptr);

        float* t = Xc; Xc = Xn; Xn = t;
        if (st == 0) Xc = X1;
    }
}

// round 13
// speedup vs baseline: 2.6259x; 1.0460x over previous
#include <cuda_runtime.h>
#include <cuda_fp16.h>
#include <cstdint>
#include <math.h>

#define MATN 4096
#define NSQL ((size_t)MATN * (size_t)MATN)

// ---------------- static device scratch ----------------
__device__ float g_X0[MATN * MATN];
__device__ float g_X1[MATN * MATN];
__device__ float g_S [MATN * MATN];
__device__ float g_P [MATN * MATN];
__device__ __half g_hA [MATN * MATN];
__device__ __half g_lA [MATN * MATN];
__device__ __half g_hAT[MATN * MATN];
__device__ __half g_lAT[MATN * MATN];
__device__ __half g_hS [MATN * MATN];
__device__ __half g_lS [MATN * MATN];
__device__ __half g_hP [MATN * MATN];
__device__ __half g_lP [MATN * MATN];
__device__ float g_v[MATN];
__device__ float g_y[MATN];
__device__ float g_part[256];
__device__ float g_scal[4];    // [1]=sigma_ray^2  [2]=tmp norm

// ---------------- helpers ----------------
__device__ __forceinline__ uint32_t smem_u32(const void* p) {
    uint32_t a;
    asm("{ .reg .u64 t; cvta.to.shared.u64 t, %1; cvt.u32.u64 %0, t; }" : "=r"(a) : "l"(p));
    return a;
}
__device__ __forceinline__ void cp16(uint32_t dst, const void* src) {
    asm volatile("cp.async.cg.shared.global [%0], [%1], 16;" :: "r"(dst), "l"(src));
}
#define CP_COMMIT() asm volatile("cp.async.commit_group;" ::: "memory")
#define CP_WAIT(N)  asm volatile("cp.async.wait_group %0;" :: "n"(N) : "memory")

#define LDSM_X4(r, a)                                                           \
    asm volatile("ldmatrix.sync.aligned.m8n8.x4.shared.b16 {%0,%1,%2,%3}, [%4];" \
        : "=r"((r)[0]), "=r"((r)[1]), "=r"((r)[2]), "=r"((r)[3]) : "r"(a))

__device__ __forceinline__ void mma_f16(float* d, const uint32_t* a,
                                        uint32_t b0, uint32_t b1) {
    asm volatile(
        "mma.sync.aligned.m16n8k16.row.col.f32.f16.f16.f32 "
        "{%0,%1,%2,%3}, {%4,%5,%6,%7}, {%8,%9}, {%0,%1,%2,%3};"
        : "+f"(d[0]), "+f"(d[1]), "+f"(d[2]), "+f"(d[3])
        : "r"(a[0]), "r"(a[1]), "r"(a[2]), "r"(a[3]), "r"(b0), "r"(b1));
}

// ---------------- fp16 tensor-core GEMM (mma.sync) ----------------
// C = sum_s A_s * B_s^T ; POLY=1: C = c2*D + c1*E + c0*I.
// TRI=1: compute only tiles with col-tile >= row-tile (upper triangle).
// Optional fused split: if Hi != null, also write half(C) (and residual to Lo).
#define BROW 80
#define ABYTES (128 * BROW)
#define BUFBYTES (2 * ABYTES)

template<int POLY, int TRI>
__global__ void __launch_bounds__(256, 2)
mma_gemm(const __half* __restrict__ A0, const __half* __restrict__ B0,
         const __half* __restrict__ A1, const __half* __restrict__ B1,
         const __half* __restrict__ A2, const __half* __restrict__ B2,
         int nseg, float* __restrict__ C, const float* __restrict__ E,
         float c0, float c1, float c2,
         __half* __restrict__ Hi, __half* __restrict__ Lo)
{
    if (TRI && (int)blockIdx.x < (int)blockIdx.y) return;
    __shared__ __align__(16) char smem[2 * BUFBYTES];
    const uint32_t sbase = smem_u32(smem);

    const int tid  = threadIdx.x;
    const int wid  = tid >> 5, lane = tid & 31;
    const int wr   = wid & 3;
    const int wc   = wid >> 2;
    const int row0 = blockIdx.y * 128;
    const int col0 = blockIdx.x * 128;

    const __half* Aseg[3] = {A0, A1, A2};
    const __half* Bseg[3] = {B0, B1, B2};

    float acc[2][8][4];
    #pragma unroll
    for (int i = 0; i < 2; ++i)
        #pragma unroll
        for (int j = 0; j < 8; ++j)
            #pragma unroll
            for (int k = 0; k < 4; ++k) acc[i][j][k] = 0.f;

    auto load_chunk = [&](int ch, int buf) {
        const int seg = ch >> 7, kc = ch & 127;
        const __half* Ap = Aseg[seg] + (size_t)row0 * MATN + kc * 32;
        const __half* Bp = Bseg[seg] + (size_t)col0 * MATN + kc * 32;
        const uint32_t sa = sbase + buf * BUFBYTES;
        const uint32_t sb = sa + ABYTES;
        #pragma unroll
        for (int p = 0; p < 2; ++p) {
            int q = tid + p * 256;
            int r = q >> 2, s = q & 3;
            cp16(sa + r * BROW + s * 16, Ap + (size_t)r * MATN + s * 8);
            cp16(sb + r * BROW + s * 16, Bp + (size_t)r * MATN + s * 8);
        }
        CP_COMMIT();
    };

    const int total = nseg * 128;
    load_chunk(0, 0);

    for (int ch = 0; ch < total; ++ch) {
        const int buf = ch & 1;
        if (ch + 1 < total) { load_chunk(ch + 1, buf ^ 1); CP_WAIT(1); }
        else                { CP_WAIT(0); }
        __syncthreads();

        const uint32_t sa = sbase + buf * BUFBYTES;
        const uint32_t sb = sa + ABYTES;
        #pragma unroll
        for (int kk = 0; kk < 2; ++kk) {
            uint32_t af[2][4], bf[4][4];
            #pragma unroll
            for (int mt = 0; mt < 2; ++mt) {
                uint32_t addr = sa + (uint32_t)(wr * 32 + mt * 16 + (lane & 15)) * BROW
                              + kk * 32 + (lane >> 4) * 16;
                LDSM_X4(af[mt], addr);
            }
            #pragma unroll
            for (int bp = 0; bp < 4; ++bp) {
                int grp = lane >> 3, wi = lane & 7;
                uint32_t addr = sb + (uint32_t)(wc * 64 + bp * 16 + wi + (grp >> 1) * 8) * BROW
                              + kk * 32 + (grp & 1) * 16;
                LDSM_X4(bf[bp], addr);
            }
            #pragma unroll
            for (int mt = 0; mt < 2; ++mt)
                #pragma unroll
                for (int nt = 0; nt < 8; ++nt)
                    mma_f16(acc[mt][nt], af[mt], bf[nt >> 1][(nt & 1) * 2],
                            bf[nt >> 1][(nt & 1) * 2 + 1]);
        }
        __syncthreads();
    }

    #pragma unroll
    for (int mt = 0; mt < 2; ++mt) {
        #pragma unroll
        for (int half = 0; half < 2; ++half) {
            const int rg = row0 + wr * 32 + mt * 16 + (lane >> 2) + half * 8;
            const size_t rowbase = (size_t)rg * MATN;
            #pragma unroll
            for (int nt = 0; nt < 8; ++nt) {
                const int cc = col0 + wc * 64 + nt * 8 + (lane & 3) * 2;
                float v0 = acc[mt][nt][half * 2 + 0];
                float v1 = acc[mt][nt][half * 2 + 1];
                if (POLY) {
                    float2 e = *reinterpret_cast<const float2*>(E + rowbase + cc);
                    v0 = c2 * v0 + c1 * e.x + ((rg == cc)     ? c0 : 0.f);
                    v1 = c2 * v1 + c1 * e.y + ((rg == cc + 1) ? c0 : 0.f);
                }
                float2 o = make_float2(v0, v1);
                *reinterpret_cast<float2*>(C + rowbase + cc) = o;
                if (Hi) {
                    __half2 hh = __floats2half2_rn(v0, v1);
                    *reinterpret_cast<__half2*>(Hi + rowbase + cc) = hh;
                    if (Lo) {
                        float l0 = v0 - __half2float(__low2half(hh));
                        float l1 = v1 - __half2float(__high2half(hh));
                        *reinterpret_cast<__half2*>(Lo + rowbase + cc) =
                            __floats2half2_rn(l0, l1);
                    }
                }
            }
        }
    }
}

// ---------------- small kernels ----------------
__global__ void k_sumsq(const float* __restrict__ x, int n, float* __restrict__ part) {
    __shared__ float sm[256];
    float acc = 0.f;
    for (int i = blockIdx.x * blockDim.x + threadIdx.x; i < n; i += gridDim.x * blockDim.x) {
        float v = x[i]; acc = fmaf(v, v, acc);
    }
    sm[threadIdx.x] = acc; __syncthreads();
    for (int s = 128; s > 0; s >>= 1) {
        if (threadIdx.x < s) sm[threadIdx.x] += sm[threadIdx.x + s];
        __syncthreads();
    }
    if (threadIdx.x == 0) part[blockIdx.x] = sm[0];
}
__global__ void k_finish(const float* __restrict__ part, float* __restrict__ dst) {
    __shared__ float sm[256];
    sm[threadIdx.x] = part[threadIdx.x]; __syncthreads();
    for (int s = 128; s > 0; s >>= 1) {
        if (threadIdx.x < s) sm[threadIdx.x] += sm[threadIdx.x + s];
        __syncthreads();
    }
    if (threadIdx.x == 0) *dst = sm[0];
}

__global__ void k_initv(float* v) {
    int j = blockIdx.x * blockDim.x + threadIdx.x;
    if (j < MATN) {
        unsigned h = (unsigned)j * 2654435761u;
        h ^= h >> 13; h *= 0x5bd1e995u; h ^= h >> 15;
        v[j] = ((float)(h & 0xFFFFu) / 65536.0f) - 0.5f + 0.001f;
    }
}
__global__ void k_normalize(float* v, const float* n2) {
    int j = blockIdx.x * blockDim.x + threadIdx.x;
    float s = rsqrtf(*n2 + 1e-30f);
    if (j < MATN) v[j] *= s;
}
__global__ void k_mvn(const float* __restrict__ H, const float* __restrict__ v,
                      float* __restrict__ y) {
    __shared__ float sm[128];
    int r = blockIdx.x;
    const float* row = H + (size_t)r * MATN;
    float acc = 0.f;
    for (int j = threadIdx.x; j < MATN; j += 128) acc = fmaf(row[j], v[j], acc);
    sm[threadIdx.x] = acc; __syncthreads();
    for (int s = 64; s > 0; s >>= 1) {
        if (threadIdx.x < s) sm[threadIdx.x] += sm[threadIdx.x + s];
        __syncthreads();
    }
    if (threadIdx.x == 0) y[r] = sm[0];
}
__global__ void k_mvt(const float* __restrict__ H, const float* __restrict__ y,
                      float* __restrict__ z) {
    __shared__ float sm[256];
    int tj = threadIdx.x & 31, gi = threadIdx.x >> 5;
    int j = blockIdx.x * 32 + tj;
    float acc = 0.f;
    for (int i = gi * 512; i < gi * 512 + 512; ++i)
        acc = fmaf(H[(size_t)i * MATN + j], y[i], acc);
    sm[threadIdx.x] = acc; __syncthreads();
    if (threadIdx.x < 32) {
        float t = 0.f;
        #pragma unroll
        for (int g = 0; g < 8; ++g) t += sm[threadIdx.x + 32 * g];
        z[j] = t;
    }
}

// split X -> (hi, lo) and transposed copies; optional prescale from g_scal[1]
__global__ void k_splitT(const float* __restrict__ X,
                         __half* __restrict__ hi, __half* __restrict__ lo,
                         __half* __restrict__ hiT, __half* __restrict__ loT,
                         int prescale) {
    __shared__ float t[32][33];
    float s = prescale ? (rsqrtf(g_scal[1] + 1e-30f) / 1.10f) : 1.0f;
    int x0 = blockIdx.x * 32, y0 = blockIdx.y * 32;
    #pragma unroll
    for (int j = 0; j < 32; j += 8) {
        int r = y0 + threadIdx.y + j, c = x0 + threadIdx.x;
        float v = X[(size_t)r * MATN + c] * s;
        t[threadIdx.y + j][threadIdx.x] = v;
        __half h = __float2half(v);
        hi[(size_t)r * MATN + c] = h;
        lo[(size_t)r * MATN + c] = __float2half(v - __half2float(h));
    }
    __syncthreads();
    #pragma unroll
    for (int j = 0; j < 32; j += 8) {
        int r = x0 + threadIdx.y + j, c = y0 + threadIdx.x;
        float v = t[threadIdx.x][threadIdx.y + j];
        __half h = __float2half(v);
        hiT[(size_t)r * MATN + c] = h;
        loT[(size_t)r * MATN + c] = __float2half(v - __half2float(h));
    }
}

// mirror upper->lower (strictly below diagonal): fp32 + hi (+ lo if wlo)
__global__ void k_mirror(float* __restrict__ M,
                         __half* __restrict__ hi, __half* __restrict__ lo, int wlo) {
    __shared__ float ta[32][33];
    int bi = blockIdx.y, bj = blockIdx.x;
    if (bj <= bi) return;
    int i0 = bi * 32, j0 = bj * 32;
    #pragma unroll
    for (int j = 0; j < 32; j += 8)
        ta[threadIdx.y + j][threadIdx.x] =
            M[(size_t)(i0 + threadIdx.y + j) * MATN + j0 + threadIdx.x];
    __syncthreads();
    #pragma unroll
    for (int j = 0; j < 32; j += 8) {
        size_t idx2 = (size_t)(j0 + threadIdx.y + j) * MATN + i0 + threadIdx.x;
        float v = ta[threadIdx.x][threadIdx.y + j];
        M[idx2] = v;
        __half h = __float2half(v);
        hi[idx2] = h;
        if (wlo) lo[idx2] = __float2half(v - __half2float(h));
    }
}

// ---------------- driver ----------------
extern "C" void kernel_launch(void* const* d_in, const int* in_sizes, int n_in,
                              void* d_out, int out_size)
{
    const float* H = (const float*)d_in[0];
    float* out = (float*)d_out;

    float *X0, *X1, *S, *P, *v, *y, *part, *scal;
    __half *hA, *lA, *hAT, *lAT, *hS, *lS, *hP, *lP;
    cudaGetSymbolAddress((void**)&X0, g_X0);   cudaGetSymbolAddress((void**)&X1, g_X1);
    cudaGetSymbolAddress((void**)&S, g_S);     cudaGetSymbolAddress((void**)&P, g_P);
    cudaGetSymbolAddress((void**)&hA, g_hA);   cudaGetSymbolAddress((void**)&lA, g_lA);
    cudaGetSymbolAddress((void**)&hAT, g_hAT); cudaGetSymbolAddress((void**)&lAT, g_lAT);
    cudaGetSymbolAddress((void**)&hS, g_hS);   cudaGetSymbolAddress((void**)&lS, g_lS);
    cudaGetSymbolAddress((void**)&hP, g_hP);   cudaGetSymbolAddress((void**)&lP, g_lP);
    cudaGetSymbolAddress((void**)&v, g_v);     cudaGetSymbolAddress((void**)&y, g_y);
    cudaGetSymbolAddress((void**)&part, g_part); cudaGetSymbolAddress((void**)&scal, g_scal);

    // --- spectral norm estimate: 10 power iterations, Rayleigh lower bound ---
    k_initv<<<(MATN + 255) / 256, 256>>>(v);
    for (int t = 0; t < 10; ++t) {
        k_sumsq<<<256, 256>>>(v, MATN, part);
        k_finish<<<1, 256>>>(part, scal + 2);
        k_normalize<<<(MATN + 255) / 256, 256>>>(v, scal + 2);
        k_mvn<<<MATN, 128>>>(H, v, y);
        k_mvt<<<MATN / 32, 256>>>(H, y, v);
    }
    k_sumsq<<<256, 256>>>(v, MATN, part);
    k_finish<<<1, 256>>>(part, scal + 2);
    k_normalize<<<(MATN + 255) / 256, 256>>>(v, scal + 2);
    k_mvn<<<MATN, 128>>>(H, v, y);
    k_sumsq<<<256, 256>>>(y, MATN, part);
    k_finish<<<1, 256>>>(part, scal + 1);   // scal[1] = sigma_ray^2

    // --- schedule: 1 x L125, 7 x LA, 1 x COMP, 2 x NS (11 steps), hardened 0.99 ---
    // steps 0..7 : raw     (raw S, raw P, X' = (Xh+Xl) * Ph, 2 segs)
    // steps 8..9 : semiraw (raw S, raw P, X' fully split, 3 segs)
    // step  10   : full    (split S, split P, X' fully split)
    const int NSTEP = 11;
    float ca[NSTEP], cb[NSTEP], cc[NSTEP];
    for (int i = 0; i < NSTEP; ++i) {
        if (i == 0)      { ca[i] = 3.115487f;  cb[i] = -5.123742f;   cc[i] = 2.327495f; }
        else if (i <= 7) { ca[i] = 3.894363f;  cb[i] = -10.007316f;  cc[i] = 7.102953f; }
        else if (i == 8) { ca[i] = 2.8426f;    cb[i] = -4.4442f;     cc[i] = 2.6015f; }
        else             { ca[i] = 1.875f;     cb[i] = -1.25f;       cc[i] = 0.375f; }
    }

    dim3 grd(MATN / 128, MATN / 128);   // (32, 32)
    dim3 g32(MATN / 32, MATN / 32);
    dim3 b32(32, 8);
    float* Xc = X0;
    float* Xn = X1;

    for (int st = 0; st < NSTEP; ++st) {
        float* dst = (st == NSTEP - 1) ? out : Xn;
        const float a = ca[st], b = cb[st], c = cc[st];
        const bool fullS = (st == NSTEP - 1);    // last step: exact split S and P
        const bool splitX = (st >= 8);           // semiraw/full: 3-seg X'

        k_splitT<<<g32, b32>>>((st == 0) ? H : Xc, hA, lA, hAT, lAT, (st == 0) ? 1 : 0);

        // S = X^T X  (upper tiles, fused split in epilogue)
        if (fullS)
            mma_gemm<0, 1><<<grd, 256>>>(hAT, hAT, hAT, lAT, lAT, hAT, 3, S, nullptr,
                                         0, 0, 0, hS, lS);
        else
            mma_gemm<0, 1><<<grd, 256>>>(hAT, hAT, hAT, hAT, hAT, hAT, 1, S, nullptr,
                                         0, 0, 0, hS, nullptr);
        k_mirror<<<g32, b32>>>(S, hS, lS, fullS ? 1 : 0);

        // P = a I + b S + c S^2  (upper tiles; b-term reads exact fp32 S)
        if (fullS)
            mma_gemm<1, 1><<<grd, 256>>>(hS, hS, hS, lS, lS, hS, 3, P, S, a, b, c,
                                         hP, lP);
        else
            mma_gemm<1, 1><<<grd, 256>>>(hS, hS, hS, hS, hS, hS, 1, P, S, a, b, c,
                                         hP, splitX ? lP : nullptr);
        k_mirror<<<g32, b32>>>(P, hP, lP, splitX ? 1 : 0);

        // X'
        if (splitX)
            mma_gemm<0, 0><<<grd, 256>>>(hA, hP, hA, lP, lA, hP, 3, dst, nullptr,
                                         0, 0, 0, nullptr, nullptr);
        else
            mma_gemm<0, 0><<<grd, 256>>>(hA, hP, lA, hP, hA, hP, 2, dst, nullptr,
                                         0, 0, 0, nullptr, nullptr);

        float* t = Xc; Xc = Xn; Xn = t;
        if (st == 0) Xc = X1;
    }
}

// round 14
// speedup vs baseline: 2.7832x; 1.0599x over previous
#include <cuda_runtime.h>
#include <cuda_fp16.h>
#include <cstdint>
#include <math.h>

#define MATN 4096
#define NSQL ((size_t)MATN * (size_t)MATN)

// ---------------- static device scratch ----------------
__device__ float g_X0[MATN * MATN];
__device__ float g_X1[MATN * MATN];
__device__ float g_S [MATN * MATN];
__device__ float g_P [MATN * MATN];
__device__ __half g_hA [MATN * MATN];
__device__ __half g_lA [MATN * MATN];
__device__ __half g_hAT[MATN * MATN];
__device__ __half g_lAT[MATN * MATN];
__device__ __half g_hS [MATN * MATN];
__device__ __half g_lS [MATN * MATN];
__device__ __half g_hP [MATN * MATN];
__device__ __half g_lP [MATN * MATN];
__device__ float g_v[MATN];
__device__ float g_y[MATN];
__device__ float g_part[256];
__device__ float g_scal[4];    // [1]=sigma_ray^2  [2]=tmp norm

// ---------------- helpers ----------------
__device__ __forceinline__ uint32_t smem_u32(const void* p) {
    uint32_t a;
    asm("{ .reg .u64 t; cvta.to.shared.u64 t, %1; cvt.u32.u64 %0, t; }" : "=r"(a) : "l"(p));
    return a;
}
__device__ __forceinline__ void cp16(uint32_t dst, const void* src) {
    asm volatile("cp.async.cg.shared.global [%0], [%1], 16;" :: "r"(dst), "l"(src));
}
#define CP_COMMIT() asm volatile("cp.async.commit_group;" ::: "memory")
#define CP_WAIT(N)  asm volatile("cp.async.wait_group %0;" :: "n"(N) : "memory")

#define LDSM_X4(r, a)                                                           \
    asm volatile("ldmatrix.sync.aligned.m8n8.x4.shared.b16 {%0,%1,%2,%3}, [%4];" \
        : "=r"((r)[0]), "=r"((r)[1]), "=r"((r)[2]), "=r"((r)[3]) : "r"(a))

__device__ __forceinline__ void mma_f16(float* d, const uint32_t* a,
                                        uint32_t b0, uint32_t b1) {
    asm volatile(
        "mma.sync.aligned.m16n8k16.row.col.f32.f16.f16.f32 "
        "{%0,%1,%2,%3}, {%4,%5,%6,%7}, {%8,%9}, {%0,%1,%2,%3};"
        : "+f"(d[0]), "+f"(d[1]), "+f"(d[2]), "+f"(d[3])
        : "r"(a[0]), "r"(a[1]), "r"(a[2]), "r"(a[3]), "r"(b0), "r"(b1));
}

// ---------------- fp16 tensor-core GEMM (mma.sync) ----------------
// C = sum_s A_s * B_s^T ; POLY=1: C = c2*D + c1*E + c0*I.
// TRI=1: compute only tiles with col-tile >= row-tile (upper triangle).
// Optional fused split: if Hi != null, also write half(C) (and residual to Lo).
#define BROW 80
#define ABYTES (128 * BROW)
#define BUFBYTES (2 * ABYTES)

template<int POLY, int TRI>
__global__ void __launch_bounds__(256, 2)
mma_gemm(const __half* __restrict__ A0, const __half* __restrict__ B0,
         const __half* __restrict__ A1, const __half* __restrict__ B1,
         const __half* __restrict__ A2, const __half* __restrict__ B2,
         int nseg, float* __restrict__ C, const float* __restrict__ E,
         float c0, float c1, float c2,
         __half* __restrict__ Hi, __half* __restrict__ Lo)
{
    if (TRI && (int)blockIdx.x < (int)blockIdx.y) return;
    __shared__ __align__(16) char smem[2 * BUFBYTES];
    const uint32_t sbase = smem_u32(smem);

    const int tid  = threadIdx.x;
    const int wid  = tid >> 5, lane = tid & 31;
    const int wr   = wid & 3;
    const int wc   = wid >> 2;
    const int row0 = blockIdx.y * 128;
    const int col0 = blockIdx.x * 128;

    const __half* Aseg[3] = {A0, A1, A2};
    const __half* Bseg[3] = {B0, B1, B2};

    float acc[2][8][4];
    #pragma unroll
    for (int i = 0; i < 2; ++i)
        #pragma unroll
        for (int j = 0; j < 8; ++j)
            #pragma unroll
            for (int k = 0; k < 4; ++k) acc[i][j][k] = 0.f;

    auto load_chunk = [&](int ch, int buf) {
        const int seg = ch >> 7, kc = ch & 127;
        const __half* Ap = Aseg[seg] + (size_t)row0 * MATN + kc * 32;
        const __half* Bp = Bseg[seg] + (size_t)col0 * MATN + kc * 32;
        const uint32_t sa = sbase + buf * BUFBYTES;
        const uint32_t sb = sa + ABYTES;
        #pragma unroll
        for (int p = 0; p < 2; ++p) {
            int q = tid + p * 256;
            int r = q >> 2, s = q & 3;
            cp16(sa + r * BROW + s * 16, Ap + (size_t)r * MATN + s * 8);
            cp16(sb + r * BROW + s * 16, Bp + (size_t)r * MATN + s * 8);
        }
        CP_COMMIT();
    };

    const int total = nseg * 128;
    load_chunk(0, 0);

    for (int ch = 0; ch < total; ++ch) {
        const int buf = ch & 1;
        if (ch + 1 < total) { load_chunk(ch + 1, buf ^ 1); CP_WAIT(1); }
        else                { CP_WAIT(0); }
        __syncthreads();

        const uint32_t sa = sbase + buf * BUFBYTES;
        const uint32_t sb = sa + ABYTES;
        #pragma unroll
        for (int kk = 0; kk < 2; ++kk) {
            uint32_t af[2][4], bf[4][4];
            #pragma unroll
            for (int mt = 0; mt < 2; ++mt) {
                uint32_t addr = sa + (uint32_t)(wr * 32 + mt * 16 + (lane & 15)) * BROW
                              + kk * 32 + (lane >> 4) * 16;
                LDSM_X4(af[mt], addr);
            }
            #pragma unroll
            for (int bp = 0; bp < 4; ++bp) {
                int grp = lane >> 3, wi = lane & 7;
                uint32_t addr = sb + (uint32_t)(wc * 64 + bp * 16 + wi + (grp >> 1) * 8) * BROW
                              + kk * 32 + (grp & 1) * 16;
                LDSM_X4(bf[bp], addr);
            }
            #pragma unroll
            for (int mt = 0; mt < 2; ++mt)
                #pragma unroll
                for (int nt = 0; nt < 8; ++nt)
                    mma_f16(acc[mt][nt], af[mt], bf[nt >> 1][(nt & 1) * 2],
                            bf[nt >> 1][(nt & 1) * 2 + 1]);
        }
        __syncthreads();
    }

    #pragma unroll
    for (int mt = 0; mt < 2; ++mt) {
        #pragma unroll
        for (int half = 0; half < 2; ++half) {
            const int rg = row0 + wr * 32 + mt * 16 + (lane >> 2) + half * 8;
            const size_t rowbase = (size_t)rg * MATN;
            #pragma unroll
            for (int nt = 0; nt < 8; ++nt) {
                const int cc = col0 + wc * 64 + nt * 8 + (lane & 3) * 2;
                float v0 = acc[mt][nt][half * 2 + 0];
                float v1 = acc[mt][nt][half * 2 + 1];
                if (POLY) {
                    float2 e = *reinterpret_cast<const float2*>(E + rowbase + cc);
                    v0 = c2 * v0 + c1 * e.x + ((rg == cc)     ? c0 : 0.f);
                    v1 = c2 * v1 + c1 * e.y + ((rg == cc + 1) ? c0 : 0.f);
                }
                float2 o = make_float2(v0, v1);
                *reinterpret_cast<float2*>(C + rowbase + cc) = o;
                if (Hi) {
                    __half2 hh = __floats2half2_rn(v0, v1);
                    *reinterpret_cast<__half2*>(Hi + rowbase + cc) = hh;
                    if (Lo) {
                        float l0 = v0 - __half2float(__low2half(hh));
                        float l1 = v1 - __half2float(__high2half(hh));
                        *reinterpret_cast<__half2*>(Lo + rowbase + cc) =
                            __floats2half2_rn(l0, l1);
                    }
                }
            }
        }
    }
}

// ---------------- small kernels ----------------
__global__ void k_sumsq(const float* __restrict__ x, int n, float* __restrict__ part) {
    __shared__ float sm[256];
    float acc = 0.f;
    for (int i = blockIdx.x * blockDim.x + threadIdx.x; i < n; i += gridDim.x * blockDim.x) {
        float v = x[i]; acc = fmaf(v, v, acc);
    }
    sm[threadIdx.x] = acc; __syncthreads();
    for (int s = 128; s > 0; s >>= 1) {
        if (threadIdx.x < s) sm[threadIdx.x] += sm[threadIdx.x + s];
        __syncthreads();
    }
    if (threadIdx.x == 0) part[blockIdx.x] = sm[0];
}
__global__ void k_finish(const float* __restrict__ part, float* __restrict__ dst) {
    __shared__ float sm[256];
    sm[threadIdx.x] = part[threadIdx.x]; __syncthreads();
    for (int s = 128; s > 0; s >>= 1) {
        if (threadIdx.x < s) sm[threadIdx.x] += sm[threadIdx.x + s];
        __syncthreads();
    }
    if (threadIdx.x == 0) *dst = sm[0];
}

__global__ void k_initv(float* v) {
    int j = blockIdx.x * blockDim.x + threadIdx.x;
    if (j < MATN) {
        unsigned h = (unsigned)j * 2654435761u;
        h ^= h >> 13; h *= 0x5bd1e995u; h ^= h >> 15;
        v[j] = ((float)(h & 0xFFFFu) / 65536.0f) - 0.5f + 0.001f;
    }
}
__global__ void k_normalize(float* v, const float* n2) {
    int j = blockIdx.x * blockDim.x + threadIdx.x;
    float s = rsqrtf(*n2 + 1e-30f);
    if (j < MATN) v[j] *= s;
}
__global__ void k_mvn(const float* __restrict__ H, const float* __restrict__ v,
                      float* __restrict__ y) {
    __shared__ float sm[128];
    int r = blockIdx.x;
    const float* row = H + (size_t)r * MATN;
    float acc = 0.f;
    for (int j = threadIdx.x; j < MATN; j += 128) acc = fmaf(row[j], v[j], acc);
    sm[threadIdx.x] = acc; __syncthreads();
    for (int s = 64; s > 0; s >>= 1) {
        if (threadIdx.x < s) sm[threadIdx.x] += sm[threadIdx.x + s];
        __syncthreads();
    }
    if (threadIdx.x == 0) y[r] = sm[0];
}
__global__ void k_mvt(const float* __restrict__ H, const float* __restrict__ y,
                      float* __restrict__ z) {
    __shared__ float sm[256];
    int tj = threadIdx.x & 31, gi = threadIdx.x >> 5;
    int j = blockIdx.x * 32 + tj;
    float acc = 0.f;
    for (int i = gi * 512; i < gi * 512 + 512; ++i)
        acc = fmaf(H[(size_t)i * MATN + j], y[i], acc);
    sm[threadIdx.x] = acc; __syncthreads();
    if (threadIdx.x < 32) {
        float t = 0.f;
        #pragma unroll
        for (int g = 0; g < 8; ++g) t += sm[threadIdx.x + 32 * g];
        z[j] = t;
    }
}

// split X -> (hi, lo) and transposed copies; optional prescale from g_scal[1]
__global__ void k_splitT(const float* __restrict__ X,
                         __half* __restrict__ hi, __half* __restrict__ lo,
                         __half* __restrict__ hiT, __half* __restrict__ loT,
                         int prescale) {
    __shared__ float t[32][33];
    float s = prescale ? (rsqrtf(g_scal[1] + 1e-30f) / 1.10f) : 1.0f;
    int x0 = blockIdx.x * 32, y0 = blockIdx.y * 32;
    #pragma unroll
    for (int j = 0; j < 32; j += 8) {
        int r = y0 + threadIdx.y + j, c = x0 + threadIdx.x;
        float v = X[(size_t)r * MATN + c] * s;
        t[threadIdx.y + j][threadIdx.x] = v;
        __half h = __float2half(v);
        hi[(size_t)r * MATN + c] = h;
        lo[(size_t)r * MATN + c] = __float2half(v - __half2float(h));
    }
    __syncthreads();
    #pragma unroll
    for (int j = 0; j < 32; j += 8) {
        int r = x0 + threadIdx.y + j, c = y0 + threadIdx.x;
        float v = t[threadIdx.x][threadIdx.y + j];
        __half h = __float2half(v);
        hiT[(size_t)r * MATN + c] = h;
        loT[(size_t)r * MATN + c] = __float2half(v - __half2float(h));
    }
}

// mirror upper->lower (strictly below diagonal): hi always, lo if wlo.
// fp32 lower triangle is never read downstream -> not written.
__global__ void k_mirror(const float* __restrict__ M,
                         __half* __restrict__ hi, __half* __restrict__ lo, int wlo) {
    __shared__ float ta[32][33];
    int bi = blockIdx.y, bj = blockIdx.x;
    if (bj <= bi) return;
    int i0 = bi * 32, j0 = bj * 32;
    #pragma unroll
    for (int j = 0; j < 32; j += 8)
        ta[threadIdx.y + j][threadIdx.x] =
            M[(size_t)(i0 + threadIdx.y + j) * MATN + j0 + threadIdx.x];
    __syncthreads();
    #pragma unroll
    for (int j = 0; j < 32; j += 8) {
        size_t idx2 = (size_t)(j0 + threadIdx.y + j) * MATN + i0 + threadIdx.x;
        float v = ta[threadIdx.x][threadIdx.y + j];
        __half h = __float2half(v);
        hi[idx2] = h;
        if (wlo) lo[idx2] = __float2half(v - __half2float(h));
    }
}

// ---------------- driver ----------------
extern "C" void kernel_launch(void* const* d_in, const int* in_sizes, int n_in,
                              void* d_out, int out_size)
{
    const float* H = (const float*)d_in[0];
    float* out = (float*)d_out;

    float *X0, *X1, *S, *P, *v, *y, *part, *scal;
    __half *hA, *lA, *hAT, *lAT, *hS, *lS, *hP, *lP;
    cudaGetSymbolAddress((void**)&X0, g_X0);   cudaGetSymbolAddress((void**)&X1, g_X1);
    cudaGetSymbolAddress((void**)&S, g_S);     cudaGetSymbolAddress((void**)&P, g_P);
    cudaGetSymbolAddress((void**)&hA, g_hA);   cudaGetSymbolAddress((void**)&lA, g_lA);
    cudaGetSymbolAddress((void**)&hAT, g_hAT); cudaGetSymbolAddress((void**)&lAT, g_lAT);
    cudaGetSymbolAddress((void**)&hS, g_hS);   cudaGetSymbolAddress((void**)&lS, g_lS);
    cudaGetSymbolAddress((void**)&hP, g_hP);   cudaGetSymbolAddress((void**)&lP, g_lP);
    cudaGetSymbolAddress((void**)&v, g_v);     cudaGetSymbolAddress((void**)&y, g_y);
    cudaGetSymbolAddress((void**)&part, g_part); cudaGetSymbolAddress((void**)&scal, g_scal);

    // --- spectral norm estimate: 10 power iterations, Rayleigh lower bound ---
    k_initv<<<(MATN + 255) / 256, 256>>>(v);
    for (int t = 0; t < 10; ++t) {
        k_sumsq<<<256, 256>>>(v, MATN, part);
        k_finish<<<1, 256>>>(part, scal + 2);
        k_normalize<<<(MATN + 255) / 256, 256>>>(v, scal + 2);
        k_mvn<<<MATN, 128>>>(H, v, y);
        k_mvt<<<MATN / 32, 256>>>(H, y, v);
    }
    k_sumsq<<<256, 256>>>(v, MATN, part);
    k_finish<<<1, 256>>>(part, scal + 2);
    k_normalize<<<(MATN + 255) / 256, 256>>>(v, scal + 2);
    k_mvn<<<MATN, 128>>>(H, v, y);
    k_sumsq<<<256, 256>>>(y, MATN, part);
    k_finish<<<1, 256>>>(part, scal + 1);   // scal[1] = sigma_ray^2

    // --- schedule: 1 x L125, 7 x LA, 1 x COMP, 2 x NS (11 steps), hardened 0.99 ---
    // All steps: raw S (1 seg), raw P (1 seg).
    // steps 0..7 : X' = (Xh+Xl) * Ph          (2 segs)
    // steps 8..10: X' = Xh*Ph + Xh*Pl + Xl*Ph (3 segs; exact split of computed P)
    const int NSTEP = 11;
    float ca[NSTEP], cb[NSTEP], cc[NSTEP];
    for (int i = 0; i < NSTEP; ++i) {
        if (i == 0)      { ca[i] = 3.115487f;  cb[i] = -5.123742f;   cc[i] = 2.327495f; }
        else if (i <= 7) { ca[i] = 3.894363f;  cb[i] = -10.007316f;  cc[i] = 7.102953f; }
        else if (i == 8) { ca[i] = 2.8426f;    cb[i] = -4.4442f;     cc[i] = 2.6015f; }
        else             { ca[i] = 1.875f;     cb[i] = -1.25f;       cc[i] = 0.375f; }
    }

    dim3 grd(MATN / 128, MATN / 128);   // (32, 32)
    dim3 g32(MATN / 32, MATN / 32);
    dim3 b32(32, 8);
    float* Xc = X0;
    float* Xn = X1;

    for (int st = 0; st < NSTEP; ++st) {
        float* dst = (st == NSTEP - 1) ? out : Xn;
        const float a = ca[st], b = cb[st], c = cc[st];
        const bool splitX = (st >= 8);

        k_splitT<<<g32, b32>>>((st == 0) ? H : Xc, hA, lA, hAT, lAT, (st == 0) ? 1 : 0);

        // S = Xh^T Xh  (upper tiles, fused hi-split in epilogue)
        mma_gemm<0, 1><<<grd, 256>>>(hAT, hAT, hAT, hAT, hAT, hAT, 1, S, nullptr,
                                     0, 0, 0, hS, nullptr);
        k_mirror<<<g32, b32>>>(S, hS, lS, 0);

        // P = a I + b S + c Sh^2  (upper tiles; b-term reads fp32 S upper)
        mma_gemm<1, 1><<<grd, 256>>>(hS, hS, hS, hS, hS, hS, 1, P, S, a, b, c,
                                     hP, splitX ? lP : nullptr);
        k_mirror<<<g32, b32>>>(P, hP, lP, splitX ? 1 : 0);

        // X'
        if (splitX)
            mma_gemm<0, 0><<<grd, 256>>>(hA, hP, hA, lP, lA, hP, 3, dst, nullptr,
                                         0, 0, 0, nullptr, nullptr);
        else
            mma_gemm<0, 0><<<grd, 256>>>(hA, hP, lA, hP, hA, hP, 2, dst, nullptr,
                                         0, 0, 0, nullptr, nullptr);

        float* t = Xc; Xc = Xn; Xn = t;
        if (st == 0) Xc = X1;
    }
}